// round 13
// baseline (speedup 1.0000x reference)
#include <cuda_runtime.h>
#include <cuda_bf16.h>
#include <cstdint>

// Problem constants
#define BB 64
#define UU 512
#define AE 1024
#define UE 256
#define AA 256           // head size
#define MTOT (BB*UU)     // 32768 rows
#define KQ 1280          // Q-proj K dim

// Pre-split inputs (bf16 hi/lo; x = hi + lo)
__device__ __nv_bfloat16 g_Ah[(size_t)MTOT * KQ], g_Al[(size_t)MTOT * KQ];   // concat(ar,own)
__device__ __nv_bfloat16 g_Eh[(size_t)MTOT * UE], g_El[(size_t)MTOT * UE];   // enemy
// Pre-transposed/split weights: Wt[n][ktot]
__device__ __nv_bfloat16 g_Wqh[256 * KQ], g_Wql[256 * KQ];
__device__ __nv_bfloat16 g_Wkh[256 * 256], g_Wkl[256 * 256];
// Q/K projections, bf16 hi/lo
__device__ __nv_bfloat16 g_Qhi[(size_t)MTOT * AA], g_Qlo[(size_t)MTOT * AA];
__device__ __nv_bfloat16 g_Khi[(size_t)MTOT * AA], g_Klo[(size_t)MTOT * AA];
// Canonicalized per-batch counts
__device__ int g_fl[BB], g_ou[BB], g_en[BB];

// ---------------------------------------------------------------------------
// Adaptive int width (JAX w/o x64 silently emits int32 despite astype(int64)).
// ---------------------------------------------------------------------------
__device__ __forceinline__ bool counts_are_64bit(const int* p) {
    bool z = true;
    #pragma unroll
    for (int i = 1; i < 64; i += 2) z &= (p[i] == 0);
    return z;
}
__global__ void prep_counts(const int* __restrict__ nro, const int* __restrict__ nre,
                            const int* __restrict__ nrf)
{
    const int t = threadIdx.x;            // 64 threads
    const bool is64 = counts_are_64bit(nro);
    const int idx = is64 ? 2 * t : t;
    g_ou[t] = nro[idx];
    g_en[t] = nre[idx];
    g_fl[t] = nrf[idx];
}

// ---------------------------------------------------------------------------
// Helpers
// ---------------------------------------------------------------------------
__device__ __forceinline__ void split_bf16(float v, __nv_bfloat16& h, __nv_bfloat16& l) {
    h = __float2bfloat16(v);
    l = __float2bfloat16(v - __bfloat162float(h));
}
__device__ __forceinline__ void split2(float f0, float f1, uint32_t& hh, uint32_t& ll) {
    __nv_bfloat16 h0, l0, h1, l1;
    split_bf16(f0, h0, l0);
    split_bf16(f1, h1, l1);
    __nv_bfloat162 H; H.x = h0; H.y = h1;
    __nv_bfloat162 L; L.x = l0; L.y = l1;
    hh = *(uint32_t*)&H;
    ll = *(uint32_t*)&L;
}
__device__ __forceinline__ uint32_t smem_u32(const void* p) {
    return (uint32_t)__cvta_generic_to_shared(p);
}
__device__ __forceinline__ void cp16(void* dst, const void* src) {
    asm volatile("cp.async.cg.shared.global [%0], [%1], 16;"
                 :: "r"(smem_u32(dst)), "l"(src));
}
__device__ __forceinline__ void cp_commit() { asm volatile("cp.async.commit_group;"); }
template<int N> __device__ __forceinline__ void cp_wait() {
    asm volatile("cp.async.wait_group %0;" :: "n"(N));
}
__device__ __forceinline__ void ldmx4(uint32_t* r, const void* ptr) {
    asm volatile("ldmatrix.sync.aligned.m8n8.x4.shared.b16 {%0,%1,%2,%3}, [%4];"
                 : "=r"(r[0]), "=r"(r[1]), "=r"(r[2]), "=r"(r[3]) : "r"(smem_u32(ptr)));
}
__device__ __forceinline__ void mma_bf16(float* d, const uint32_t* a, uint32_t b0, uint32_t b1) {
    asm volatile("mma.sync.aligned.m16n8k16.row.col.f32.bf16.bf16.f32 "
                 "{%0,%1,%2,%3}, {%4,%5,%6,%7}, {%8,%9}, {%0,%1,%2,%3};"
                 : "+f"(d[0]), "+f"(d[1]), "+f"(d[2]), "+f"(d[3])
                 : "r"(a[0]), "r"(a[1]), "r"(a[2]), "r"(a[3]), "r"(b0), "r"(b1));
}

// ===========================================================================
// Pre-split: fp32 [rows][cols] -> bf16 hi/lo into [rows][ldd] at column off.
// mode 0: Q-side rows (gated by fl/ou, 128-row granularity)
// mode 1: K-side rows (gated by en,    128-row granularity)
// ===========================================================================
__global__ void __launch_bounds__(256)
presplit(const float* __restrict__ src, int cols,
         __nv_bfloat16* __restrict__ dh, __nv_bfloat16* __restrict__ dl,
         int ldd, int off, int total4, int mode)
{
    int idx = blockIdx.x * 256 + threadIdx.x;
    if (idx >= total4) return;
    const int c4 = cols >> 2;
    int row = idx / c4, c = (idx - row * c4) * 4;

    const int b = row >> 9;
    const int L = (row & 511) & ~127;      // 128-aligned local block start
    if (mode == 0) {
        if (!(L < g_ou[b] && L + 128 > g_fl[b])) return;
    } else {
        if (L >= g_en[b]) return;
    }

    float4 v = *(const float4*)&src[(size_t)row * cols + c];
    uint32_t h0, l0, h1, l1;
    split2(v.x, v.y, h0, l0);
    split2(v.z, v.w, h1, l1);
    const size_t o = (size_t)row * ldd + off + c;
    uint2 H; H.x = h0; H.y = h1;
    uint2 L2; L2.x = l0; L2.y = l1;
    *(uint2*)&dh[o] = H;
    *(uint2*)&dl[o] = L2;
}

// W transpose + split: W[k][256] fp32 -> Wt_hi/lo[n][ktot] bf16
__global__ void __launch_bounds__(256)
wconvert(const float* __restrict__ W, int ktot,
         __nv_bfloat16* __restrict__ Wh, __nv_bfloat16* __restrict__ Wl)
{
    __shared__ float t[32][33];
    const int kb = blockIdx.x * 32, nb = blockIdx.y * 32;
    const int tx = threadIdx.x & 31, ty = threadIdx.x >> 5;
    #pragma unroll
    for (int i = ty; i < 32; i += 8)
        t[i][tx] = W[(size_t)(kb + i) * 256 + nb + tx];
    __syncthreads();
    #pragma unroll
    for (int i = ty; i < 32; i += 8) {
        __nv_bfloat16 h, l;
        split_bf16(t[tx][i], h, l);
        Wh[(size_t)(nb + i) * ktot + kb + tx] = h;
        Wl[(size_t)(nb + i) * ktot + kb + tx] = l;
    }
}

// ===========================================================================
// Projection GEMM (bf16 split-3, all-cp.async staging, masked-block skip):
//   C[M,256] = A[M,ktot] @ Wt^T + bias    (A, Wt already bf16 hi/lo)
// Block 128(m) x 128(n), BK=32, 8 warps of 64x32. 2-stage cp.async ring.
// __launch_bounds__(256,2): 2 CTAs/SM so one CTA's MMA hides the other's
// barrier/LDSM stalls.
// kind 0: Q (skip if 128-row block has no valid rows); kind 1: K (skip >= en).
// ===========================================================================
#define PLD 40                       // tile row stride (bf16): 80B, conflict-free
#define TILE_B (128 * PLD * 2)       // 10240 bytes per tile
#define STAGE_B (4 * TILE_B)         // Ah, Al, Wh, Wl
#define PSM_TOTAL (2 * STAGE_B)      // 81920 (x2 CTAs = 160KB/SM, fits)

__global__ void __launch_bounds__(256, 2)
proj_bf3(const __nv_bfloat16* __restrict__ Abh, const __nv_bfloat16* __restrict__ Abl,
         int ktot,
         const __nv_bfloat16* __restrict__ Wth, const __nv_bfloat16* __restrict__ Wtl,
         const float* __restrict__ bias,
         __nv_bfloat16* __restrict__ Chi, __nv_bfloat16* __restrict__ Clo,
         int kind)
{
    extern __shared__ __align__(16) char sm[];

    const int row0 = blockIdx.y * 128;
    {   // masked-block skip (block-uniform)
        const int b = row0 >> 9, local0 = row0 & 511;
        if (kind == 0) {
            if (!(local0 < g_ou[b] && local0 + 128 > g_fl[b])) return;
        } else {
            if (local0 >= g_en[b]) return;
        }
    }

    const int tid  = threadIdx.x;
    const int warp = tid >> 5, lane = tid & 31;
    const int col0 = blockIdx.x * 128;

    const int wm = (warp & 1) * 64;
    const int wn = (warp >> 1) * 32;

    const int u0 = tid * 2;

    auto prefetch = [&](int it) {
        char* buf = sm + (it & 1) * STAGE_B;
        const int kb = it * 32;
        #pragma unroll
        for (int j = 0; j < 2; ++j) {
            const int u = u0 + j;
            const int r = u >> 2;
            const int seg = (u & 3) * 8;
            char* dst = buf + r * (PLD * 2) + seg * 2;
            const size_t ga = (size_t)(row0 + r) * ktot + kb + seg;
            const size_t gw = (size_t)(col0 + r) * ktot + kb + seg;
            cp16(dst,                Abh + ga);
            cp16(dst + TILE_B,       Abl + ga);
            cp16(dst + 2 * TILE_B,   Wth + gw);
            cp16(dst + 3 * TILE_B,   Wtl + gw);
        }
        cp_commit();
    };

    prefetch(0);

    const int lrow = lane & 15;
    const int lcol = (lane >> 4) * 8;
    const int n_it = ktot / 32;

    float acc[4][4][4] = {};

    for (int it = 0; it < n_it; ++it) {
        const bool more = it + 1 < n_it;
        if (more) prefetch(it + 1);
        if (more) cp_wait<1>(); else cp_wait<0>();
        __syncthreads();

        const char* buf = sm + (it & 1) * STAGE_B;
        const __nv_bfloat16* Ah = (const __nv_bfloat16*)buf;
        const __nv_bfloat16* Al = (const __nv_bfloat16*)(buf + TILE_B);
        const __nv_bfloat16* Wh = (const __nv_bfloat16*)(buf + 2 * TILE_B);
        const __nv_bfloat16* Wl = (const __nv_bfloat16*)(buf + 3 * TILE_B);

        #pragma unroll
        for (int kc = 0; kc < 32; kc += 16) {
            uint32_t ah[4][4], al2[4][4], bh[2][4], bl[2][4];
            #pragma unroll
            for (int mi = 0; mi < 4; ++mi) {
                ldmx4(ah[mi],  &Ah[(wm + mi * 16 + lrow) * PLD + kc + lcol]);
                ldmx4(al2[mi], &Al[(wm + mi * 16 + lrow) * PLD + kc + lcol]);
            }
            #pragma unroll
            for (int ni = 0; ni < 2; ++ni) {
                ldmx4(bh[ni], &Wh[(wn + ni * 16 + lrow) * PLD + kc + lcol]);
                ldmx4(bl[ni], &Wl[(wn + ni * 16 + lrow) * PLD + kc + lcol]);
            }
            #pragma unroll
            for (int mi = 0; mi < 4; ++mi)
                #pragma unroll
                for (int ni = 0; ni < 2; ++ni)
                    #pragma unroll
                    for (int t = 0; t < 2; ++t) {
                        float* d = acc[mi][ni * 2 + t];
                        mma_bf16(d, ah[mi],  bh[ni][t], bh[ni][t + 2]);
                        mma_bf16(d, ah[mi],  bl[ni][t], bl[ni][t + 2]);
                        mma_bf16(d, al2[mi], bh[ni][t], bh[ni][t + 2]);
                    }
        }
        __syncthreads();
    }

    #pragma unroll
    for (int mi = 0; mi < 4; ++mi)
        #pragma unroll
        for (int p = 0; p < 4; ++p) {
            const int c = col0 + wn + p * 8 + (lane & 3) * 2;
            const float b0 = bias[c], b1 = bias[c + 1];
            #pragma unroll
            for (int h = 0; h < 2; ++h) {
                const int row = row0 + wm + mi * 16 + (lane >> 2) + h * 8;
                float v0 = acc[mi][p][h * 2 + 0] + b0;
                float v1 = acc[mi][p][h * 2 + 1] + b1;
                uint32_t hh, ll;
                split2(v0, v1, hh, ll);
                *(uint32_t*)&Chi[(size_t)row * AA + c] = hh;
                *(uint32_t*)&Clo[(size_t)row * AA + c] = ll;
            }
        }
}

// ===========================================================================
// Fused attention + softmax with mask-driven skipping.
// Block = (batch b, 64 query rows). Fully-masked row-block -> uniform 1/512.
// Key chunks beyond nr_units_enemy skipped; masked logits = exactly 0.
// ===========================================================================
#define LDQ (AA + 8)
#define LDB 24
#define LDS 516

#define Q_BYTES    (64 * LDQ * 2)
#define STG_BYTES  (128 * LDB * 2)
#define SM_QH 0
#define SM_QL (SM_QH + Q_BYTES)
#define SM_B0 (SM_QL + Q_BYTES)
#define SM_S  (SM_B0 + 4 * STG_BYTES)
#define SM_TOTAL (SM_S + 64 * LDS * 4)

#define UNIFORM_P 0.001953125f   // 1/512

__global__ void __launch_bounds__(256)
attn_fused(float* __restrict__ out)
{
    extern __shared__ __align__(16) char sm[];
    __nv_bfloat16* Qh = (__nv_bfloat16*)(sm + SM_QH);
    __nv_bfloat16* Ql = (__nv_bfloat16*)(sm + SM_QL);
    float* S = (float*)(sm + SM_S);

    const int tid  = threadIdx.x;
    const int warp = tid >> 5, lane = tid & 31;
    const int b    = blockIdx.y;
    const int row0 = blockIdx.x * 64;

    const int fl = g_fl[b], ou = g_ou[b], en = g_en[b];
    float* outb = out + (size_t)b * UU * UU + (size_t)row0 * UU;

    // Fully-masked row block: softmax of ~0 logits == uniform. Write & leave.
    if (!(row0 < ou && row0 + 64 > fl)) {
        float4 u; u.x = u.y = u.z = u.w = UNIFORM_P;
        #pragma unroll
        for (int i = 0; i < 32; ++i)
            ((float4*)outb)[tid + i * 256] = u;
        return;
    }

    const int nch  = min(4, (en + 127) >> 7);   // live 128-key chunks
    const int n_it = nch * 16;

    const __nv_bfloat16* gQh = g_Qhi + (size_t)b * UU * AA;
    const __nv_bfloat16* gQl = g_Qlo + (size_t)b * UU * AA;
    const __nv_bfloat16* gKh = g_Khi + (size_t)b * UU * AA;
    const __nv_bfloat16* gKl = g_Klo + (size_t)b * UU * AA;

    const int krow = tid >> 1;
    const int koff = (tid & 1) * 8;
    auto prefetch = [&](int it) {
        const int kc = it >> 4, kk = (it & 15) * 16, buf = it & 1;
        __nv_bfloat16* dh = (__nv_bfloat16*)(sm + SM_B0 + (2 * buf + 0) * STG_BYTES);
        __nv_bfloat16* dl = (__nv_bfloat16*)(sm + SM_B0 + (2 * buf + 1) * STG_BYTES);
        const size_t g = (size_t)(kc * 128 + krow) * AA + kk + koff;
        cp16(&dh[krow * LDB + koff], &gKh[g]);
        cp16(&dl[krow * LDB + koff], &gKl[g]);
        cp_commit();
    };

    if (n_it > 0) {
        #pragma unroll
        for (int i = 0; i < 8; ++i) {
            int idx = tid + i * 256;
            int r = idx >> 5;
            int c = (idx & 31) * 8;
            *(uint4*)&Qh[r * LDQ + c] = *(const uint4*)&gQh[(size_t)(row0 + r) * AA + c];
            *(uint4*)&Ql[r * LDQ + c] = *(const uint4*)&gQl[(size_t)(row0 + r) * AA + c];
        }
        prefetch(0);
    }

    const int wq = (warp & 1) * 32;
    const int wk = (warp >> 1) * 32;
    const int lrow = lane & 15;
    const int lcol = (lane >> 4) * 8;

    float acc[2][4][4] = {};

    for (int it = 0; it < n_it; ++it) {
        const bool more = it + 1 < n_it;
        if (more) prefetch(it + 1);
        if (more) cp_wait<1>(); else cp_wait<0>();
        __syncthreads();

        const int kc = it >> 4, buf = it & 1;
        const int kk = (it & 15) * 16;
        const __nv_bfloat16* Bhb = (const __nv_bfloat16*)(sm + SM_B0 + (2 * buf + 0) * STG_BYTES);
        const __nv_bfloat16* Blb = (const __nv_bfloat16*)(sm + SM_B0 + (2 * buf + 1) * STG_BYTES);

        uint32_t ah[2][4], al2[2][4], bh[2][4], bl[2][4];
        #pragma unroll
        for (int mi = 0; mi < 2; ++mi) {
            ldmx4(ah[mi],  &Qh[(wq + mi * 16 + lrow) * LDQ + kk + lcol]);
            ldmx4(al2[mi], &Ql[(wq + mi * 16 + lrow) * LDQ + kk + lcol]);
        }
        #pragma unroll
        for (int p = 0; p < 2; ++p) {
            ldmx4(bh[p], &Bhb[(wk + p * 16 + lrow) * LDB + lcol]);
            ldmx4(bl[p], &Blb[(wk + p * 16 + lrow) * LDB + lcol]);
        }
        #pragma unroll
        for (int mi = 0; mi < 2; ++mi)
            #pragma unroll
            for (int p = 0; p < 2; ++p)
                #pragma unroll
                for (int t = 0; t < 2; ++t) {
                    float* d = acc[mi][p * 2 + t];
                    mma_bf16(d, ah[mi],  bh[p][t], bh[p][t + 2]);
                    mma_bf16(d, ah[mi],  bl[p][t], bl[p][t + 2]);
                    mma_bf16(d, al2[mi], bh[p][t], bh[p][t + 2]);
                }

        if ((it & 15) == 15) {
            #pragma unroll
            for (int mi = 0; mi < 2; ++mi)
                #pragma unroll
                for (int ni = 0; ni < 4; ++ni) {
                    const int c = kc * 128 + wk + ni * 8 + (lane & 3) * 2;
                    #pragma unroll
                    for (int hh = 0; hh < 2; ++hh) {
                        const int row = wq + mi * 16 + (lane >> 2) + hh * 8;
                        float2 v;
                        v.x = acc[mi][ni][hh * 2 + 0] * 0.0625f;
                        v.y = acc[mi][ni][hh * 2 + 1] * 0.0625f;
                        *(float2*)&S[row * LDS + c] = v;
                        acc[mi][ni][hh * 2 + 0] = 0.f;
                        acc[mi][ni][hh * 2 + 1] = 0.f;
                    }
                }
        }
        __syncthreads();
    }

    // ---- masked softmax; masked logits are exactly 0 (matches s*1e-9) ----
    #pragma unroll 1
    for (int r8 = 0; r8 < 8; ++r8) {
        const int row = warp * 8 + r8;
        const int grow = row0 + row;
        const bool row_ok = (grow >= fl) && (grow < ou);

        if (!row_ok) {
            float4 u; u.x = u.y = u.z = u.w = UNIFORM_P;
            #pragma unroll
            for (int j = 0; j < 4; ++j)
                *(float4*)&outb[(size_t)row * UU + lane * 4 + j * 128] = u;
            continue;
        }

        float4 v[4];
        float m = 0.f;                      // masked zeros participate in max
        #pragma unroll
        for (int j = 0; j < 4; ++j) {
            const int c = lane * 4 + j * 128;
            float4 s = *(const float4*)&S[row * LDS + c];   // garbage ok; selected out
            #pragma unroll
            for (int e = 0; e < 4; ++e) {
                const bool ok = (c + e) < en;
                float x = ok ? (&s.x)[e] : 0.f;
                (&v[j].x)[e] = x;
                m = fmaxf(m, x);
            }
        }
        #pragma unroll
        for (int o = 16; o > 0; o >>= 1)
            m = fmaxf(m, __shfl_xor_sync(0xffffffffu, m, o));

        float sum = 0.f;
        #pragma unroll
        for (int j = 0; j < 4; ++j)
            #pragma unroll
            for (int e = 0; e < 4; ++e) {
                float x = __expf((&v[j].x)[e] - m);
                (&v[j].x)[e] = x;
                sum += x;
            }
        #pragma unroll
        for (int o = 16; o > 0; o >>= 1)
            sum += __shfl_xor_sync(0xffffffffu, sum, o);

        const float inv = 1.0f / sum;
        #pragma unroll
        for (int j = 0; j < 4; ++j) {
            v[j].x *= inv; v[j].y *= inv; v[j].z *= inv; v[j].w *= inv;
            *(float4*)&outb[(size_t)row * UU + lane * 4 + j * 128] = v[j];
        }
    }
}

// ---------------------------------------------------------------------------
extern "C" void kernel_launch(void* const* d_in, const int* in_sizes, int n_in,
                              void* d_out, int out_size)
{
    const float* ar    = (const float*)d_in[0];
    const float* own   = (const float*)d_in[1];
    const float* enemy = (const float*)d_in[2];
    const int* nro     = (const int*)d_in[3];
    const int* nre     = (const int*)d_in[4];
    const int* nrf     = (const int*)d_in[5];
    const float* Wq    = (const float*)d_in[6];
    const float* bq    = (const float*)d_in[7];
    const float* Wk    = (const float*)d_in[8];
    const float* bk    = (const float*)d_in[9];
    float* out = (float*)d_out;

    __nv_bfloat16 *ah, *al, *eh, *el, *wqh, *wql, *wkh, *wkl, *qh, *ql, *kh, *kl;
    cudaGetSymbolAddress((void**)&ah, g_Ah);
    cudaGetSymbolAddress((void**)&al, g_Al);
    cudaGetSymbolAddress((void**)&eh, g_Eh);
    cudaGetSymbolAddress((void**)&el, g_El);
    cudaGetSymbolAddress((void**)&wqh, g_Wqh);
    cudaGetSymbolAddress((void**)&wql, g_Wql);
    cudaGetSymbolAddress((void**)&wkh, g_Wkh);
    cudaGetSymbolAddress((void**)&wkl, g_Wkl);
    cudaGetSymbolAddress((void**)&qh, g_Qhi);
    cudaGetSymbolAddress((void**)&ql, g_Qlo);
    cudaGetSymbolAddress((void**)&kh, g_Khi);
    cudaGetSymbolAddress((void**)&kl, g_Klo);

    cudaFuncSetAttribute(proj_bf3, cudaFuncAttributeMaxDynamicSharedMemorySize, PSM_TOTAL);
    cudaFuncSetAttribute(attn_fused, cudaFuncAttributeMaxDynamicSharedMemorySize, SM_TOTAL);

    // ---- canonicalize counts, then pre-split inputs and weights ----
    prep_counts<<<1, 64>>>(nro, nre, nrf);
    {
        int t4 = MTOT * (AE / 4);
        presplit<<<(t4 + 255) / 256, 256>>>(ar, AE, ah, al, KQ, 0, t4, 0);
    }
    {
        int t4 = MTOT * (UE / 4);
        presplit<<<(t4 + 255) / 256, 256>>>(own, UE, ah, al, KQ, AE, t4, 0);
        presplit<<<(t4 + 255) / 256, 256>>>(enemy, UE, eh, el, UE, 0, t4, 1);
    }
    wconvert<<<dim3(KQ / 32, 8), 256>>>(Wq, KQ, wqh, wql);
    wconvert<<<dim3(256 / 32, 8), 256>>>(Wk, 256, wkh, wkl);

    // ---- projections (bf16 split-3 HMMA, masked-block skip, 2 CTA/SM) ----
    proj_bf3<<<dim3(2, MTOT / 128), 256, PSM_TOTAL>>>(ah, al, KQ, wqh, wql, bq, qh, ql, 0);
    proj_bf3<<<dim3(2, MTOT / 128), 256, PSM_TOTAL>>>(eh, el, UE, wkh, wkl, bk, kh, kl, 1);

    // ---- fused scores + mask + softmax (mask-skipping) ----
    attn_fused<<<dim3(UU / 64, BB), 256, SM_TOTAL>>>(out);
}

// round 14
// speedup vs baseline: 1.4805x; 1.4805x over previous
#include <cuda_runtime.h>
#include <cuda_bf16.h>
#include <cstdint>

// Problem constants
#define BB 64
#define UU 512
#define AE 1024
#define UE 256
#define AA 256           // head size
#define MTOT (BB*UU)     // 32768 rows
#define KQ 1280          // Q-proj K dim

// Pre-split inputs (bf16 hi/lo; x = hi + lo)
__device__ __nv_bfloat16 g_Ah[(size_t)MTOT * KQ], g_Al[(size_t)MTOT * KQ];   // concat(ar,own)
__device__ __nv_bfloat16 g_Eh[(size_t)MTOT * UE], g_El[(size_t)MTOT * UE];   // enemy
// Pre-transposed/split weights: Wt[n][ktot]
__device__ __nv_bfloat16 g_Wqh[256 * KQ], g_Wql[256 * KQ];
__device__ __nv_bfloat16 g_Wkh[256 * 256], g_Wkl[256 * 256];
// Q/K projections, bf16 hi/lo
__device__ __nv_bfloat16 g_Qhi[(size_t)MTOT * AA], g_Qlo[(size_t)MTOT * AA];
__device__ __nv_bfloat16 g_Khi[(size_t)MTOT * AA], g_Klo[(size_t)MTOT * AA];
// Canonicalized per-batch counts
__device__ int g_fl[BB], g_ou[BB], g_en[BB];

// ---------------------------------------------------------------------------
// Adaptive int width (JAX w/o x64 silently emits int32 despite astype(int64)).
// ---------------------------------------------------------------------------
__device__ __forceinline__ bool counts_are_64bit(const int* p) {
    bool z = true;
    #pragma unroll
    for (int i = 1; i < 64; i += 2) z &= (p[i] == 0);
    return z;
}
__global__ void prep_counts(const int* __restrict__ nro, const int* __restrict__ nre,
                            const int* __restrict__ nrf)
{
    const int t = threadIdx.x;            // 64 threads
    const bool is64 = counts_are_64bit(nro);
    const int idx = is64 ? 2 * t : t;
    g_ou[t] = nro[idx];
    g_en[t] = nre[idx];
    g_fl[t] = nrf[idx];
}

// ---------------------------------------------------------------------------
// Helpers
// ---------------------------------------------------------------------------
__device__ __forceinline__ void split_bf16(float v, __nv_bfloat16& h, __nv_bfloat16& l) {
    h = __float2bfloat16(v);
    l = __float2bfloat16(v - __bfloat162float(h));
}
__device__ __forceinline__ void split2(float f0, float f1, uint32_t& hh, uint32_t& ll) {
    __nv_bfloat16 h0, l0, h1, l1;
    split_bf16(f0, h0, l0);
    split_bf16(f1, h1, l1);
    __nv_bfloat162 H; H.x = h0; H.y = h1;
    __nv_bfloat162 L; L.x = l0; L.y = l1;
    hh = *(uint32_t*)&H;
    ll = *(uint32_t*)&L;
}
__device__ __forceinline__ uint32_t smem_u32(const void* p) {
    return (uint32_t)__cvta_generic_to_shared(p);
}
__device__ __forceinline__ void cp16(void* dst, const void* src) {
    asm volatile("cp.async.cg.shared.global [%0], [%1], 16;"
                 :: "r"(smem_u32(dst)), "l"(src));
}
__device__ __forceinline__ void cp_commit() { asm volatile("cp.async.commit_group;"); }
template<int N> __device__ __forceinline__ void cp_wait() {
    asm volatile("cp.async.wait_group %0;" :: "n"(N));
}
__device__ __forceinline__ void ldmx4(uint32_t* r, const void* ptr) {
    asm volatile("ldmatrix.sync.aligned.m8n8.x4.shared.b16 {%0,%1,%2,%3}, [%4];"
                 : "=r"(r[0]), "=r"(r[1]), "=r"(r[2]), "=r"(r[3]) : "r"(smem_u32(ptr)));
}
__device__ __forceinline__ void mma_bf16(float* d, const uint32_t* a, uint32_t b0, uint32_t b1) {
    asm volatile("mma.sync.aligned.m16n8k16.row.col.f32.bf16.bf16.f32 "
                 "{%0,%1,%2,%3}, {%4,%5,%6,%7}, {%8,%9}, {%0,%1,%2,%3};"
                 : "+f"(d[0]), "+f"(d[1]), "+f"(d[2]), "+f"(d[3])
                 : "r"(a[0]), "r"(a[1]), "r"(a[2]), "r"(a[3]), "r"(b0), "r"(b1));
}

// ===========================================================================
// Pre-split: fp32 [rows][cols] -> bf16 hi/lo into [rows][ldd] at column off.
// mode 0: Q-side rows (gated by fl/ou, 128-row granularity)
// mode 1: K-side rows (gated by en,    128-row granularity)
// ===========================================================================
__global__ void __launch_bounds__(256)
presplit(const float* __restrict__ src, int cols,
         __nv_bfloat16* __restrict__ dh, __nv_bfloat16* __restrict__ dl,
         int ldd, int off, int total4, int mode)
{
    int idx = blockIdx.x * 256 + threadIdx.x;
    if (idx >= total4) return;
    const int c4 = cols >> 2;
    int row = idx / c4, c = (idx - row * c4) * 4;

    const int b = row >> 9;
    const int L = (row & 511) & ~127;      // 128-aligned local block start
    if (mode == 0) {
        if (!(L < g_ou[b] && L + 128 > g_fl[b])) return;
    } else {
        if (L >= g_en[b]) return;
    }

    float4 v = *(const float4*)&src[(size_t)row * cols + c];
    uint32_t h0, l0, h1, l1;
    split2(v.x, v.y, h0, l0);
    split2(v.z, v.w, h1, l1);
    const size_t o = (size_t)row * ldd + off + c;
    uint2 H; H.x = h0; H.y = h1;
    uint2 L2; L2.x = l0; L2.y = l1;
    *(uint2*)&dh[o] = H;
    *(uint2*)&dl[o] = L2;
}

// W transpose + split: W[k][256] fp32 -> Wt_hi/lo[n][ktot] bf16
__global__ void __launch_bounds__(256)
wconvert(const float* __restrict__ W, int ktot,
         __nv_bfloat16* __restrict__ Wh, __nv_bfloat16* __restrict__ Wl)
{
    __shared__ float t[32][33];
    const int kb = blockIdx.x * 32, nb = blockIdx.y * 32;
    const int tx = threadIdx.x & 31, ty = threadIdx.x >> 5;
    #pragma unroll
    for (int i = ty; i < 32; i += 8)
        t[i][tx] = W[(size_t)(kb + i) * 256 + nb + tx];
    __syncthreads();
    #pragma unroll
    for (int i = ty; i < 32; i += 8) {
        __nv_bfloat16 h, l;
        split_bf16(t[tx][i], h, l);
        Wh[(size_t)(nb + i) * ktot + kb + tx] = h;
        Wl[(size_t)(nb + i) * ktot + kb + tx] = l;
    }
}

// ===========================================================================
// Projection GEMM (bf16 split-3, all-cp.async staging, masked-block skip):
//   C[M,256] = A[M,ktot] @ Wt^T + bias    (A, Wt already bf16 hi/lo)
// Block 128(m) x 128(n), BK=32, 8 warps of 64x32. 2-stage cp.async ring.
// NOTE: natural occupancy is already 2 CTA/SM (regs 94, smem 80KB); forcing
// __launch_bounds__(256,2) caps regs at 128 and spills the accumulators
// (R13: 312 -> 463us). Keep default bounds.
// kind 0: Q (skip if 128-row block has no valid rows); kind 1: K (skip >= en).
// ===========================================================================
#define PLD 40                       // tile row stride (bf16): 80B, conflict-free
#define TILE_B (128 * PLD * 2)       // 10240 bytes per tile
#define STAGE_B (4 * TILE_B)         // Ah, Al, Wh, Wl
#define PSM_TOTAL (2 * STAGE_B)      // 81920

__global__ void __launch_bounds__(256)
proj_bf3(const __nv_bfloat16* __restrict__ Abh, const __nv_bfloat16* __restrict__ Abl,
         int ktot,
         const __nv_bfloat16* __restrict__ Wth, const __nv_bfloat16* __restrict__ Wtl,
         const float* __restrict__ bias,
         __nv_bfloat16* __restrict__ Chi, __nv_bfloat16* __restrict__ Clo,
         int kind)
{
    extern __shared__ __align__(16) char sm[];

    const int row0 = blockIdx.y * 128;
    {   // masked-block skip (block-uniform)
        const int b = row0 >> 9, local0 = row0 & 511;
        if (kind == 0) {
            if (!(local0 < g_ou[b] && local0 + 128 > g_fl[b])) return;
        } else {
            if (local0 >= g_en[b]) return;
        }
    }

    const int tid  = threadIdx.x;
    const int warp = tid >> 5, lane = tid & 31;
    const int col0 = blockIdx.x * 128;

    const int wm = (warp & 1) * 64;
    const int wn = (warp >> 1) * 32;

    const int u0 = tid * 2;

    auto prefetch = [&](int it) {
        char* buf = sm + (it & 1) * STAGE_B;
        const int kb = it * 32;
        #pragma unroll
        for (int j = 0; j < 2; ++j) {
            const int u = u0 + j;
            const int r = u >> 2;
            const int seg = (u & 3) * 8;
            char* dst = buf + r * (PLD * 2) + seg * 2;
            const size_t ga = (size_t)(row0 + r) * ktot + kb + seg;
            const size_t gw = (size_t)(col0 + r) * ktot + kb + seg;
            cp16(dst,                Abh + ga);
            cp16(dst + TILE_B,       Abl + ga);
            cp16(dst + 2 * TILE_B,   Wth + gw);
            cp16(dst + 3 * TILE_B,   Wtl + gw);
        }
        cp_commit();
    };

    prefetch(0);

    const int lrow = lane & 15;
    const int lcol = (lane >> 4) * 8;
    const int n_it = ktot / 32;

    float acc[4][4][4] = {};

    for (int it = 0; it < n_it; ++it) {
        const bool more = it + 1 < n_it;
        if (more) prefetch(it + 1);
        if (more) cp_wait<1>(); else cp_wait<0>();
        __syncthreads();

        const char* buf = sm + (it & 1) * STAGE_B;
        const __nv_bfloat16* Ah = (const __nv_bfloat16*)buf;
        const __nv_bfloat16* Al = (const __nv_bfloat16*)(buf + TILE_B);
        const __nv_bfloat16* Wh = (const __nv_bfloat16*)(buf + 2 * TILE_B);
        const __nv_bfloat16* Wl = (const __nv_bfloat16*)(buf + 3 * TILE_B);

        #pragma unroll
        for (int kc = 0; kc < 32; kc += 16) {
            uint32_t ah[4][4], al2[4][4], bh[2][4], bl[2][4];
            #pragma unroll
            for (int mi = 0; mi < 4; ++mi) {
                ldmx4(ah[mi],  &Ah[(wm + mi * 16 + lrow) * PLD + kc + lcol]);
                ldmx4(al2[mi], &Al[(wm + mi * 16 + lrow) * PLD + kc + lcol]);
            }
            #pragma unroll
            for (int ni = 0; ni < 2; ++ni) {
                ldmx4(bh[ni], &Wh[(wn + ni * 16 + lrow) * PLD + kc + lcol]);
                ldmx4(bl[ni], &Wl[(wn + ni * 16 + lrow) * PLD + kc + lcol]);
            }
            #pragma unroll
            for (int mi = 0; mi < 4; ++mi)
                #pragma unroll
                for (int ni = 0; ni < 2; ++ni)
                    #pragma unroll
                    for (int t = 0; t < 2; ++t) {
                        float* d = acc[mi][ni * 2 + t];
                        mma_bf16(d, ah[mi],  bh[ni][t], bh[ni][t + 2]);
                        mma_bf16(d, ah[mi],  bl[ni][t], bl[ni][t + 2]);
                        mma_bf16(d, al2[mi], bh[ni][t], bh[ni][t + 2]);
                    }
        }
        __syncthreads();
    }

    #pragma unroll
    for (int mi = 0; mi < 4; ++mi)
        #pragma unroll
        for (int p = 0; p < 4; ++p) {
            const int c = col0 + wn + p * 8 + (lane & 3) * 2;
            const float b0 = bias[c], b1 = bias[c + 1];
            #pragma unroll
            for (int h = 0; h < 2; ++h) {
                const int row = row0 + wm + mi * 16 + (lane >> 2) + h * 8;
                float v0 = acc[mi][p][h * 2 + 0] + b0;
                float v1 = acc[mi][p][h * 2 + 1] + b1;
                uint32_t hh, ll;
                split2(v0, v1, hh, ll);
                *(uint32_t*)&Chi[(size_t)row * AA + c] = hh;
                *(uint32_t*)&Clo[(size_t)row * AA + c] = ll;
            }
        }
}

// ===========================================================================
// Fused attention + softmax with mask-driven skipping.
// Block = (batch b, 64 query rows). Fully-masked row-block -> uniform 1/512.
// Key chunks beyond nr_units_enemy skipped; masked logits = exactly 0.
// Q tile loaded via cp.async (own group) so it overlaps K chunk-0 staging.
// ===========================================================================
#define LDQ (AA + 8)      // 264 bf16 -> row stride 528B (16B-aligned)
#define LDB 24
#define LDS 516

#define Q_BYTES    (64 * LDQ * 2)
#define STG_BYTES  (128 * LDB * 2)
#define SM_QH 0
#define SM_QL (SM_QH + Q_BYTES)
#define SM_B0 (SM_QL + Q_BYTES)
#define SM_S  (SM_B0 + 4 * STG_BYTES)
#define SM_TOTAL (SM_S + 64 * LDS * 4)

#define UNIFORM_P 0.001953125f   // 1/512

__global__ void __launch_bounds__(256)
attn_fused(float* __restrict__ out)
{
    extern __shared__ __align__(16) char sm[];
    __nv_bfloat16* Qh = (__nv_bfloat16*)(sm + SM_QH);
    __nv_bfloat16* Ql = (__nv_bfloat16*)(sm + SM_QL);
    float* S = (float*)(sm + SM_S);

    const int tid  = threadIdx.x;
    const int warp = tid >> 5, lane = tid & 31;
    const int b    = blockIdx.y;
    const int row0 = blockIdx.x * 64;

    const int fl = g_fl[b], ou = g_ou[b], en = g_en[b];
    float* outb = out + (size_t)b * UU * UU + (size_t)row0 * UU;

    // Fully-masked row block: softmax of ~0 logits == uniform. Write & leave.
    if (!(row0 < ou && row0 + 64 > fl)) {
        float4 u; u.x = u.y = u.z = u.w = UNIFORM_P;
        #pragma unroll
        for (int i = 0; i < 32; ++i)
            ((float4*)outb)[tid + i * 256] = u;
        return;
    }

    const int nch  = min(4, (en + 127) >> 7);   // live 128-key chunks
    const int n_it = nch * 16;

    const __nv_bfloat16* gQh = g_Qhi + (size_t)b * UU * AA;
    const __nv_bfloat16* gQl = g_Qlo + (size_t)b * UU * AA;
    const __nv_bfloat16* gKh = g_Khi + (size_t)b * UU * AA;
    const __nv_bfloat16* gKl = g_Klo + (size_t)b * UU * AA;

    const int krow = tid >> 1;
    const int koff = (tid & 1) * 8;
    auto prefetch = [&](int it) {
        const int kc = it >> 4, kk = (it & 15) * 16, buf = it & 1;
        __nv_bfloat16* dh = (__nv_bfloat16*)(sm + SM_B0 + (2 * buf + 0) * STG_BYTES);
        __nv_bfloat16* dl = (__nv_bfloat16*)(sm + SM_B0 + (2 * buf + 1) * STG_BYTES);
        const size_t g = (size_t)(kc * 128 + krow) * AA + kk + koff;
        cp16(&dh[krow * LDB + koff], &gKh[g]);
        cp16(&dl[krow * LDB + koff], &gKl[g]);
        cp_commit();
    };

    if (n_it > 0) {
        // Q tile via cp.async (group 0) — overlaps with K chunk-0 staging.
        #pragma unroll
        for (int i = 0; i < 8; ++i) {
            int idx = tid + i * 256;
            int r = idx >> 5;
            int c = (idx & 31) * 8;
            cp16(&Qh[r * LDQ + c], &gQh[(size_t)(row0 + r) * AA + c]);
            cp16(&Ql[r * LDQ + c], &gQl[(size_t)(row0 + r) * AA + c]);
        }
        cp_commit();
        prefetch(0);
    }

    const int wq = (warp & 1) * 32;
    const int wk = (warp >> 1) * 32;
    const int lrow = lane & 15;
    const int lcol = (lane >> 4) * 8;

    float acc[2][4][4] = {};

    for (int it = 0; it < n_it; ++it) {
        const bool more = it + 1 < n_it;
        if (more) prefetch(it + 1);
        if (more) cp_wait<1>(); else cp_wait<0>();
        __syncthreads();

        const int kc = it >> 4, buf = it & 1;
        const int kk = (it & 15) * 16;
        const __nv_bfloat16* Bhb = (const __nv_bfloat16*)(sm + SM_B0 + (2 * buf + 0) * STG_BYTES);
        const __nv_bfloat16* Blb = (const __nv_bfloat16*)(sm + SM_B0 + (2 * buf + 1) * STG_BYTES);

        uint32_t ah[2][4], al2[2][4], bh[2][4], bl[2][4];
        #pragma unroll
        for (int mi = 0; mi < 2; ++mi) {
            ldmx4(ah[mi],  &Qh[(wq + mi * 16 + lrow) * LDQ + kk + lcol]);
            ldmx4(al2[mi], &Ql[(wq + mi * 16 + lrow) * LDQ + kk + lcol]);
        }
        #pragma unroll
        for (int p = 0; p < 2; ++p) {
            ldmx4(bh[p], &Bhb[(wk + p * 16 + lrow) * LDB + lcol]);
            ldmx4(bl[p], &Blb[(wk + p * 16 + lrow) * LDB + lcol]);
        }
        #pragma unroll
        for (int mi = 0; mi < 2; ++mi)
            #pragma unroll
            for (int p = 0; p < 2; ++p)
                #pragma unroll
                for (int t = 0; t < 2; ++t) {
                    float* d = acc[mi][p * 2 + t];
                    mma_bf16(d, ah[mi],  bh[p][t], bh[p][t + 2]);
                    mma_bf16(d, ah[mi],  bl[p][t], bl[p][t + 2]);
                    mma_bf16(d, al2[mi], bh[p][t], bh[p][t + 2]);
                }

        if ((it & 15) == 15) {
            #pragma unroll
            for (int mi = 0; mi < 2; ++mi)
                #pragma unroll
                for (int ni = 0; ni < 4; ++ni) {
                    const int c = kc * 128 + wk + ni * 8 + (lane & 3) * 2;
                    #pragma unroll
                    for (int hh = 0; hh < 2; ++hh) {
                        const int row = wq + mi * 16 + (lane >> 2) + hh * 8;
                        float2 v;
                        v.x = acc[mi][ni][hh * 2 + 0] * 0.0625f;
                        v.y = acc[mi][ni][hh * 2 + 1] * 0.0625f;
                        *(float2*)&S[row * LDS + c] = v;
                        acc[mi][ni][hh * 2 + 0] = 0.f;
                        acc[mi][ni][hh * 2 + 1] = 0.f;
                    }
                }
        }
        __syncthreads();
    }

    // ---- masked softmax; masked logits are exactly 0 (matches s*1e-9) ----
    #pragma unroll 1
    for (int r8 = 0; r8 < 8; ++r8) {
        const int row = warp * 8 + r8;
        const int grow = row0 + row;
        const bool row_ok = (grow >= fl) && (grow < ou);

        if (!row_ok) {
            float4 u; u.x = u.y = u.z = u.w = UNIFORM_P;
            #pragma unroll
            for (int j = 0; j < 4; ++j)
                *(float4*)&outb[(size_t)row * UU + lane * 4 + j * 128] = u;
            continue;
        }

        float4 v[4];
        float m = 0.f;                      // masked zeros participate in max
        #pragma unroll
        for (int j = 0; j < 4; ++j) {
            const int c = lane * 4 + j * 128;
            float4 s = *(const float4*)&S[row * LDS + c];   // garbage ok; selected out
            #pragma unroll
            for (int e = 0; e < 4; ++e) {
                const bool ok = (c + e) < en;
                float x = ok ? (&s.x)[e] : 0.f;
                (&v[j].x)[e] = x;
                m = fmaxf(m, x);
            }
        }
        #pragma unroll
        for (int o = 16; o > 0; o >>= 1)
            m = fmaxf(m, __shfl_xor_sync(0xffffffffu, m, o));

        float sum = 0.f;
        #pragma unroll
        for (int j = 0; j < 4; ++j)
            #pragma unroll
            for (int e = 0; e < 4; ++e) {
                float x = __expf((&v[j].x)[e] - m);
                (&v[j].x)[e] = x;
                sum += x;
            }
        #pragma unroll
        for (int o = 16; o > 0; o >>= 1)
            sum += __shfl_xor_sync(0xffffffffu, sum, o);

        const float inv = 1.0f / sum;
        #pragma unroll
        for (int j = 0; j < 4; ++j) {
            v[j].x *= inv; v[j].y *= inv; v[j].z *= inv; v[j].w *= inv;
            *(float4*)&outb[(size_t)row * UU + lane * 4 + j * 128] = v[j];
        }
    }
}

// ---------------------------------------------------------------------------
extern "C" void kernel_launch(void* const* d_in, const int* in_sizes, int n_in,
                              void* d_out, int out_size)
{
    const float* ar    = (const float*)d_in[0];
    const float* own   = (const float*)d_in[1];
    const float* enemy = (const float*)d_in[2];
    const int* nro     = (const int*)d_in[3];
    const int* nre     = (const int*)d_in[4];
    const int* nrf     = (const int*)d_in[5];
    const float* Wq    = (const float*)d_in[6];
    const float* bq    = (const float*)d_in[7];
    const float* Wk    = (const float*)d_in[8];
    const float* bk    = (const float*)d_in[9];
    float* out = (float*)d_out;

    __nv_bfloat16 *ah, *al, *eh, *el, *wqh, *wql, *wkh, *wkl, *qh, *ql, *kh, *kl;
    cudaGetSymbolAddress((void**)&ah, g_Ah);
    cudaGetSymbolAddress((void**)&al, g_Al);
    cudaGetSymbolAddress((void**)&eh, g_Eh);
    cudaGetSymbolAddress((void**)&el, g_El);
    cudaGetSymbolAddress((void**)&wqh, g_Wqh);
    cudaGetSymbolAddress((void**)&wql, g_Wql);
    cudaGetSymbolAddress((void**)&wkh, g_Wkh);
    cudaGetSymbolAddress((void**)&wkl, g_Wkl);
    cudaGetSymbolAddress((void**)&qh, g_Qhi);
    cudaGetSymbolAddress((void**)&ql, g_Qlo);
    cudaGetSymbolAddress((void**)&kh, g_Khi);
    cudaGetSymbolAddress((void**)&kl, g_Klo);

    cudaFuncSetAttribute(proj_bf3, cudaFuncAttributeMaxDynamicSharedMemorySize, PSM_TOTAL);
    cudaFuncSetAttribute(attn_fused, cudaFuncAttributeMaxDynamicSharedMemorySize, SM_TOTAL);

    // ---- canonicalize counts, then pre-split inputs and weights ----
    prep_counts<<<1, 64>>>(nro, nre, nrf);
    {
        int t4 = MTOT * (AE / 4);
        presplit<<<(t4 + 255) / 256, 256>>>(ar, AE, ah, al, KQ, 0, t4, 0);
    }
    {
        int t4 = MTOT * (UE / 4);
        presplit<<<(t4 + 255) / 256, 256>>>(own, UE, ah, al, KQ, AE, t4, 0);
        presplit<<<(t4 + 255) / 256, 256>>>(enemy, UE, eh, el, UE, 0, t4, 1);
    }
    wconvert<<<dim3(KQ / 32, 8), 256>>>(Wq, KQ, wqh, wql);
    wconvert<<<dim3(256 / 32, 8), 256>>>(Wk, 256, wkh, wkl);

    // ---- projections (bf16 split-3 HMMA, masked-block skip) ----
    proj_bf3<<<dim3(2, MTOT / 128), 256, PSM_TOTAL>>>(ah, al, KQ, wqh, wql, bq, qh, ql, 0);
    proj_bf3<<<dim3(2, MTOT / 128), 256, PSM_TOTAL>>>(eh, el, UE, wkh, wkl, bk, kh, kl, 1);

    // ---- fused scores + mask + softmax (mask-skipping) ----
    attn_fused<<<dim3(UU / 64, BB), 256, SM_TOTAL>>>(out);
}

// round 15
// speedup vs baseline: 1.5443x; 1.0431x over previous
#include <cuda_runtime.h>
#include <cuda_bf16.h>
#include <cstdint>

// Problem constants
#define BB 64
#define UU 512
#define AE 1024
#define UE 256
#define AA 256           // head size
#define MTOT (BB*UU)     // 32768 rows
#define KQ 1280          // Q-proj K dim

// Pre-split inputs (bf16 hi/lo; x = hi + lo)
__device__ __nv_bfloat16 g_Ah[(size_t)MTOT * KQ], g_Al[(size_t)MTOT * KQ];   // concat(ar,own)
__device__ __nv_bfloat16 g_Eh[(size_t)MTOT * UE], g_El[(size_t)MTOT * UE];   // enemy
// Pre-transposed/split weights: Wt[n][ktot]
__device__ __nv_bfloat16 g_Wqh[256 * KQ], g_Wql[256 * KQ];
__device__ __nv_bfloat16 g_Wkh[256 * 256], g_Wkl[256 * 256];
// Q/K projections, bf16 hi/lo
__device__ __nv_bfloat16 g_Qhi[(size_t)MTOT * AA], g_Qlo[(size_t)MTOT * AA];
__device__ __nv_bfloat16 g_Khi[(size_t)MTOT * AA], g_Klo[(size_t)MTOT * AA];
// Canonicalized per-batch counts
__device__ int g_fl[BB], g_ou[BB], g_en[BB];

// ---------------------------------------------------------------------------
// Adaptive int width (JAX w/o x64 silently emits int32 despite astype(int64)).
// ---------------------------------------------------------------------------
__device__ __forceinline__ bool counts_are_64bit(const int* p) {
    bool z = true;
    #pragma unroll
    for (int i = 1; i < 64; i += 2) z &= (p[i] == 0);
    return z;
}
__global__ void prep_counts(const int* __restrict__ nro, const int* __restrict__ nre,
                            const int* __restrict__ nrf)
{
    const int t = threadIdx.x;            // 64 threads
    const bool is64 = counts_are_64bit(nro);
    const int idx = is64 ? 2 * t : t;
    g_ou[t] = nro[idx];
    g_en[t] = nre[idx];
    g_fl[t] = nrf[idx];
}

// ---------------------------------------------------------------------------
// Helpers
// ---------------------------------------------------------------------------
__device__ __forceinline__ void split_bf16(float v, __nv_bfloat16& h, __nv_bfloat16& l) {
    h = __float2bfloat16(v);
    l = __float2bfloat16(v - __bfloat162float(h));
}
__device__ __forceinline__ void split2(float f0, float f1, uint32_t& hh, uint32_t& ll) {
    __nv_bfloat16 h0, l0, h1, l1;
    split_bf16(f0, h0, l0);
    split_bf16(f1, h1, l1);
    __nv_bfloat162 H; H.x = h0; H.y = h1;
    __nv_bfloat162 L; L.x = l0; L.y = l1;
    hh = *(uint32_t*)&H;
    ll = *(uint32_t*)&L;
}
__device__ __forceinline__ uint32_t smem_u32(const void* p) {
    return (uint32_t)__cvta_generic_to_shared(p);
}
__device__ __forceinline__ void cp16(void* dst, const void* src) {
    asm volatile("cp.async.cg.shared.global [%0], [%1], 16;"
                 :: "r"(smem_u32(dst)), "l"(src));
}
__device__ __forceinline__ void cp_commit() { asm volatile("cp.async.commit_group;"); }
template<int N> __device__ __forceinline__ void cp_wait() {
    asm volatile("cp.async.wait_group %0;" :: "n"(N));
}
__device__ __forceinline__ void ldmx4(uint32_t* r, const void* ptr) {
    asm volatile("ldmatrix.sync.aligned.m8n8.x4.shared.b16 {%0,%1,%2,%3}, [%4];"
                 : "=r"(r[0]), "=r"(r[1]), "=r"(r[2]), "=r"(r[3]) : "r"(smem_u32(ptr)));
}
__device__ __forceinline__ void mma_bf16(float* d, const uint32_t* a, uint32_t b0, uint32_t b1) {
    asm volatile("mma.sync.aligned.m16n8k16.row.col.f32.bf16.bf16.f32 "
                 "{%0,%1,%2,%3}, {%4,%5,%6,%7}, {%8,%9}, {%0,%1,%2,%3};"
                 : "+f"(d[0]), "+f"(d[1]), "+f"(d[2]), "+f"(d[3])
                 : "r"(a[0]), "r"(a[1]), "r"(a[2]), "r"(a[3]), "r"(b0), "r"(b1));
}

// ===========================================================================
// Fused pre-split: one grid covers ar -> A[:,0:1024], own -> A[:,1024:1280],
// enemy -> E[:,0:256]. Region decoded from block index.
// ===========================================================================
#define T4_AR  (MTOT * (AE / 4))     // 8388608
#define T4_OWN (MTOT * (UE / 4))     // 2097152
#define B_AR   (T4_AR / 256)         // 32768 blocks
#define B_OWN  (T4_OWN / 256)        // 8192 blocks
#define B_ALL  (B_AR + 2 * B_OWN)    // 49152

__global__ void __launch_bounds__(256)
presplit_all(const float* __restrict__ ar, const float* __restrict__ own,
             const float* __restrict__ enemy)
{
    int blk = blockIdx.x;
    const float* src;
    __nv_bfloat16 *dh, *dl;
    int cols, ldd, off, mode, idx;

    if (blk < B_AR) {
        src = ar;    dh = g_Ah; dl = g_Al; cols = AE; ldd = KQ; off = 0;   mode = 0;
        idx = blk * 256 + threadIdx.x;
    } else if (blk < B_AR + B_OWN) {
        src = own;   dh = g_Ah; dl = g_Al; cols = UE; ldd = KQ; off = AE;  mode = 0;
        idx = (blk - B_AR) * 256 + threadIdx.x;
    } else {
        src = enemy; dh = g_Eh; dl = g_El; cols = UE; ldd = UE; off = 0;   mode = 1;
        idx = (blk - B_AR - B_OWN) * 256 + threadIdx.x;
    }

    const int c4 = cols >> 2;
    int row = idx / c4, c = (idx - row * c4) * 4;

    const int b = row >> 9;
    const int L = (row & 511) & ~127;      // 128-aligned local block start
    if (mode == 0) {
        if (!(L < g_ou[b] && L + 128 > g_fl[b])) return;
    } else {
        if (L >= g_en[b]) return;
    }

    float4 v = *(const float4*)&src[(size_t)row * cols + c];
    uint32_t h0, l0, h1, l1;
    split2(v.x, v.y, h0, l0);
    split2(v.z, v.w, h1, l1);
    const size_t o = (size_t)row * ldd + off + c;
    uint2 H; H.x = h0; H.y = h1;
    uint2 L2; L2.x = l0; L2.y = l1;
    *(uint2*)&dh[o] = H;
    *(uint2*)&dl[o] = L2;
}

// W transpose + split: W[k][256] fp32 -> Wt_hi/lo[n][ktot] bf16
__global__ void __launch_bounds__(256)
wconvert(const float* __restrict__ W, int ktot,
         __nv_bfloat16* __restrict__ Wh, __nv_bfloat16* __restrict__ Wl)
{
    __shared__ float t[32][33];
    const int kb = blockIdx.x * 32, nb = blockIdx.y * 32;
    const int tx = threadIdx.x & 31, ty = threadIdx.x >> 5;
    #pragma unroll
    for (int i = ty; i < 32; i += 8)
        t[i][tx] = W[(size_t)(kb + i) * 256 + nb + tx];
    __syncthreads();
    #pragma unroll
    for (int i = ty; i < 32; i += 8) {
        __nv_bfloat16 h, l;
        split_bf16(t[tx][i], h, l);
        Wh[(size_t)(nb + i) * ktot + kb + tx] = h;
        Wl[(size_t)(nb + i) * ktot + kb + tx] = l;
    }
}

// ===========================================================================
// Dual projection GEMM (Q and K in ONE launch; z=0 -> Q, z=1 -> K):
//   Q = A[M,1280] @ Wq^T + bq ; K = E[M,256] @ Wk^T + bk   (bf16 split-3)
// Block 128(m) x 128(n), BK=32, 8 warps of 64x32. 2-stage cp.async ring.
// K blocks (ktot=256) are short and fill Q-proj's tail wave.
// NOTE: do NOT force __launch_bounds__(256,2) — natural occupancy is already
// 2 CTA/SM; the forced reg cap spills accumulators (R13: 312 -> 463us).
// ===========================================================================
#define PLD 40                       // tile row stride (bf16): 80B, conflict-free
#define TILE_B (128 * PLD * 2)       // 10240 bytes per tile
#define STAGE_B (4 * TILE_B)         // Ah, Al, Wh, Wl
#define PSM_TOTAL (2 * STAGE_B)      // 81920

__global__ void __launch_bounds__(256)
proj_dual(const float* __restrict__ bq, const float* __restrict__ bk)
{
    extern __shared__ __align__(16) char sm[];

    const int z = blockIdx.z;                 // 0 = Q, 1 = K
    const int row0 = blockIdx.y * 128;
    {   // masked-block skip (block-uniform)
        const int b = row0 >> 9, local0 = row0 & 511;
        if (z == 0) {
            if (!(local0 < g_ou[b] && local0 + 128 > g_fl[b])) return;
        } else {
            if (local0 >= g_en[b]) return;
        }
    }

    const __nv_bfloat16* Abh = z ? g_Eh  : g_Ah;
    const __nv_bfloat16* Abl = z ? g_El  : g_Al;
    const __nv_bfloat16* Wth = z ? g_Wkh : g_Wqh;
    const __nv_bfloat16* Wtl = z ? g_Wkl : g_Wql;
    const float*         bias = z ? bk : bq;
    __nv_bfloat16* Chi = z ? g_Khi : g_Qhi;
    __nv_bfloat16* Clo = z ? g_Klo : g_Qlo;
    const int ktot = z ? UE : KQ;

    const int tid  = threadIdx.x;
    const int warp = tid >> 5, lane = tid & 31;
    const int col0 = blockIdx.x * 128;

    const int wm = (warp & 1) * 64;
    const int wn = (warp >> 1) * 32;

    const int u0 = tid * 2;

    auto prefetch = [&](int it) {
        char* buf = sm + (it & 1) * STAGE_B;
        const int kb = it * 32;
        #pragma unroll
        for (int j = 0; j < 2; ++j) {
            const int u = u0 + j;
            const int r = u >> 2;
            const int seg = (u & 3) * 8;
            char* dst = buf + r * (PLD * 2) + seg * 2;
            const size_t ga = (size_t)(row0 + r) * ktot + kb + seg;
            const size_t gw = (size_t)(col0 + r) * ktot + kb + seg;
            cp16(dst,                Abh + ga);
            cp16(dst + TILE_B,       Abl + ga);
            cp16(dst + 2 * TILE_B,   Wth + gw);
            cp16(dst + 3 * TILE_B,   Wtl + gw);
        }
        cp_commit();
    };

    prefetch(0);

    const int lrow = lane & 15;
    const int lcol = (lane >> 4) * 8;
    const int n_it = ktot / 32;

    float acc[4][4][4] = {};

    for (int it = 0; it < n_it; ++it) {
        const bool more = it + 1 < n_it;
        if (more) prefetch(it + 1);
        if (more) cp_wait<1>(); else cp_wait<0>();
        __syncthreads();

        const char* buf = sm + (it & 1) * STAGE_B;
        const __nv_bfloat16* Ah = (const __nv_bfloat16*)buf;
        const __nv_bfloat16* Al = (const __nv_bfloat16*)(buf + TILE_B);
        const __nv_bfloat16* Wh = (const __nv_bfloat16*)(buf + 2 * TILE_B);
        const __nv_bfloat16* Wl = (const __nv_bfloat16*)(buf + 3 * TILE_B);

        #pragma unroll
        for (int kc = 0; kc < 32; kc += 16) {
            uint32_t ah[4][4], al2[4][4], bh[2][4], bl[2][4];
            #pragma unroll
            for (int mi = 0; mi < 4; ++mi) {
                ldmx4(ah[mi],  &Ah[(wm + mi * 16 + lrow) * PLD + kc + lcol]);
                ldmx4(al2[mi], &Al[(wm + mi * 16 + lrow) * PLD + kc + lcol]);
            }
            #pragma unroll
            for (int ni = 0; ni < 2; ++ni) {
                ldmx4(bh[ni], &Wh[(wn + ni * 16 + lrow) * PLD + kc + lcol]);
                ldmx4(bl[ni], &Wl[(wn + ni * 16 + lrow) * PLD + kc + lcol]);
            }
            #pragma unroll
            for (int mi = 0; mi < 4; ++mi)
                #pragma unroll
                for (int ni = 0; ni < 2; ++ni)
                    #pragma unroll
                    for (int t = 0; t < 2; ++t) {
                        float* d = acc[mi][ni * 2 + t];
                        mma_bf16(d, ah[mi],  bh[ni][t], bh[ni][t + 2]);
                        mma_bf16(d, ah[mi],  bl[ni][t], bl[ni][t + 2]);
                        mma_bf16(d, al2[mi], bh[ni][t], bh[ni][t + 2]);
                    }
        }
        __syncthreads();
    }

    #pragma unroll
    for (int mi = 0; mi < 4; ++mi)
        #pragma unroll
        for (int p = 0; p < 4; ++p) {
            const int c = col0 + wn + p * 8 + (lane & 3) * 2;
            const float b0 = bias[c], b1 = bias[c + 1];
            #pragma unroll
            for (int h = 0; h < 2; ++h) {
                const int row = row0 + wm + mi * 16 + (lane >> 2) + h * 8;
                float v0 = acc[mi][p][h * 2 + 0] + b0;
                float v1 = acc[mi][p][h * 2 + 1] + b1;
                uint32_t hh, ll;
                split2(v0, v1, hh, ll);
                *(uint32_t*)&Chi[(size_t)row * AA + c] = hh;
                *(uint32_t*)&Clo[(size_t)row * AA + c] = ll;
            }
        }
}

// ===========================================================================
// Fused attention + softmax with mask-driven skipping (unchanged hot loop).
// ===========================================================================
#define LDQ (AA + 8)      // 264 bf16 -> row stride 528B (16B-aligned)
#define LDB 24
#define LDS 516

#define Q_BYTES    (64 * LDQ * 2)
#define STG_BYTES  (128 * LDB * 2)
#define SM_QH 0
#define SM_QL (SM_QH + Q_BYTES)
#define SM_B0 (SM_QL + Q_BYTES)
#define SM_S  (SM_B0 + 4 * STG_BYTES)
#define SM_TOTAL (SM_S + 64 * LDS * 4)

#define UNIFORM_P 0.001953125f   // 1/512

__global__ void __launch_bounds__(256)
attn_fused(float* __restrict__ out)
{
    extern __shared__ __align__(16) char sm[];
    __nv_bfloat16* Qh = (__nv_bfloat16*)(sm + SM_QH);
    __nv_bfloat16* Ql = (__nv_bfloat16*)(sm + SM_QL);
    float* S = (float*)(sm + SM_S);

    const int tid  = threadIdx.x;
    const int warp = tid >> 5, lane = tid & 31;
    const int b    = blockIdx.y;
    const int row0 = blockIdx.x * 64;

    const int fl = g_fl[b], ou = g_ou[b], en = g_en[b];
    float* outb = out + (size_t)b * UU * UU + (size_t)row0 * UU;

    // Fully-masked row block: softmax of ~0 logits == uniform. Write & leave.
    if (!(row0 < ou && row0 + 64 > fl)) {
        float4 u; u.x = u.y = u.z = u.w = UNIFORM_P;
        #pragma unroll
        for (int i = 0; i < 32; ++i)
            ((float4*)outb)[tid + i * 256] = u;
        return;
    }

    const int nch  = min(4, (en + 127) >> 7);   // live 128-key chunks
    const int n_it = nch * 16;

    const __nv_bfloat16* gQh = g_Qhi + (size_t)b * UU * AA;
    const __nv_bfloat16* gQl = g_Qlo + (size_t)b * UU * AA;
    const __nv_bfloat16* gKh = g_Khi + (size_t)b * UU * AA;
    const __nv_bfloat16* gKl = g_Klo + (size_t)b * UU * AA;

    const int krow = tid >> 1;
    const int koff = (tid & 1) * 8;
    auto prefetch = [&](int it) {
        const int kc = it >> 4, kk = (it & 15) * 16, buf = it & 1;
        __nv_bfloat16* dh = (__nv_bfloat16*)(sm + SM_B0 + (2 * buf + 0) * STG_BYTES);
        __nv_bfloat16* dl = (__nv_bfloat16*)(sm + SM_B0 + (2 * buf + 1) * STG_BYTES);
        const size_t g = (size_t)(kc * 128 + krow) * AA + kk + koff;
        cp16(&dh[krow * LDB + koff], &gKh[g]);
        cp16(&dl[krow * LDB + koff], &gKl[g]);
        cp_commit();
    };

    if (n_it > 0) {
        // Q tile via cp.async (group 0) — overlaps with K chunk-0 staging.
        #pragma unroll
        for (int i = 0; i < 8; ++i) {
            int idx = tid + i * 256;
            int r = idx >> 5;
            int c = (idx & 31) * 8;
            cp16(&Qh[r * LDQ + c], &gQh[(size_t)(row0 + r) * AA + c]);
            cp16(&Ql[r * LDQ + c], &gQl[(size_t)(row0 + r) * AA + c]);
        }
        cp_commit();
        prefetch(0);
    }

    const int wq = (warp & 1) * 32;
    const int wk = (warp >> 1) * 32;
    const int lrow = lane & 15;
    const int lcol = (lane >> 4) * 8;

    float acc[2][4][4] = {};

    for (int it = 0; it < n_it; ++it) {
        const bool more = it + 1 < n_it;
        if (more) prefetch(it + 1);
        if (more) cp_wait<1>(); else cp_wait<0>();
        __syncthreads();

        const int kc = it >> 4, buf = it & 1;
        const int kk = (it & 15) * 16;
        const __nv_bfloat16* Bhb = (const __nv_bfloat16*)(sm + SM_B0 + (2 * buf + 0) * STG_BYTES);
        const __nv_bfloat16* Blb = (const __nv_bfloat16*)(sm + SM_B0 + (2 * buf + 1) * STG_BYTES);

        uint32_t ah[2][4], al2[2][4], bh[2][4], bl[2][4];
        #pragma unroll
        for (int mi = 0; mi < 2; ++mi) {
            ldmx4(ah[mi],  &Qh[(wq + mi * 16 + lrow) * LDQ + kk + lcol]);
            ldmx4(al2[mi], &Ql[(wq + mi * 16 + lrow) * LDQ + kk + lcol]);
        }
        #pragma unroll
        for (int p = 0; p < 2; ++p) {
            ldmx4(bh[p], &Bhb[(wk + p * 16 + lrow) * LDB + lcol]);
            ldmx4(bl[p], &Blb[(wk + p * 16 + lrow) * LDB + lcol]);
        }
        #pragma unroll
        for (int mi = 0; mi < 2; ++mi)
            #pragma unroll
            for (int p = 0; p < 2; ++p)
                #pragma unroll
                for (int t = 0; t < 2; ++t) {
                    float* d = acc[mi][p * 2 + t];
                    mma_bf16(d, ah[mi],  bh[p][t], bh[p][t + 2]);
                    mma_bf16(d, ah[mi],  bl[p][t], bl[p][t + 2]);
                    mma_bf16(d, al2[mi], bh[p][t], bh[p][t + 2]);
                }

        if ((it & 15) == 15) {
            #pragma unroll
            for (int mi = 0; mi < 2; ++mi)
                #pragma unroll
                for (int ni = 0; ni < 4; ++ni) {
                    const int c = kc * 128 + wk + ni * 8 + (lane & 3) * 2;
                    #pragma unroll
                    for (int hh = 0; hh < 2; ++hh) {
                        const int row = wq + mi * 16 + (lane >> 2) + hh * 8;
                        float2 v;
                        v.x = acc[mi][ni][hh * 2 + 0] * 0.0625f;
                        v.y = acc[mi][ni][hh * 2 + 1] * 0.0625f;
                        *(float2*)&S[row * LDS + c] = v;
                        acc[mi][ni][hh * 2 + 0] = 0.f;
                        acc[mi][ni][hh * 2 + 1] = 0.f;
                    }
                }
        }
        __syncthreads();
    }

    // ---- masked softmax; masked logits are exactly 0 (matches s*1e-9) ----
    #pragma unroll 1
    for (int r8 = 0; r8 < 8; ++r8) {
        const int row = warp * 8 + r8;
        const int grow = row0 + row;
        const bool row_ok = (grow >= fl) && (grow < ou);

        if (!row_ok) {
            float4 u; u.x = u.y = u.z = u.w = UNIFORM_P;
            #pragma unroll
            for (int j = 0; j < 4; ++j)
                *(float4*)&outb[(size_t)row * UU + lane * 4 + j * 128] = u;
            continue;
        }

        float4 v[4];
        float m = 0.f;                      // masked zeros participate in max
        #pragma unroll
        for (int j = 0; j < 4; ++j) {
            const int c = lane * 4 + j * 128;
            float4 s = *(const float4*)&S[row * LDS + c];   // garbage ok; selected out
            #pragma unroll
            for (int e = 0; e < 4; ++e) {
                const bool ok = (c + e) < en;
                float x = ok ? (&s.x)[e] : 0.f;
                (&v[j].x)[e] = x;
                m = fmaxf(m, x);
            }
        }
        #pragma unroll
        for (int o = 16; o > 0; o >>= 1)
            m = fmaxf(m, __shfl_xor_sync(0xffffffffu, m, o));

        float sum = 0.f;
        #pragma unroll
        for (int j = 0; j < 4; ++j)
            #pragma unroll
            for (int e = 0; e < 4; ++e) {
                float x = __expf((&v[j].x)[e] - m);
                (&v[j].x)[e] = x;
                sum += x;
            }
        #pragma unroll
        for (int o = 16; o > 0; o >>= 1)
            sum += __shfl_xor_sync(0xffffffffu, sum, o);

        const float inv = 1.0f / sum;
        #pragma unroll
        for (int j = 0; j < 4; ++j) {
            v[j].x *= inv; v[j].y *= inv; v[j].z *= inv; v[j].w *= inv;
            *(float4*)&outb[(size_t)row * UU + lane * 4 + j * 128] = v[j];
        }
    }
}

// ---------------------------------------------------------------------------
extern "C" void kernel_launch(void* const* d_in, const int* in_sizes, int n_in,
                              void* d_out, int out_size)
{
    const float* ar    = (const float*)d_in[0];
    const float* own   = (const float*)d_in[1];
    const float* enemy = (const float*)d_in[2];
    const int* nro     = (const int*)d_in[3];
    const int* nre     = (const int*)d_in[4];
    const int* nrf     = (const int*)d_in[5];
    const float* Wq    = (const float*)d_in[6];
    const float* bq    = (const float*)d_in[7];
    const float* Wk    = (const float*)d_in[8];
    const float* bk    = (const float*)d_in[9];
    float* out = (float*)d_out;

    __nv_bfloat16 *wqh, *wql, *wkh, *wkl;
    cudaGetSymbolAddress((void**)&wqh, g_Wqh);
    cudaGetSymbolAddress((void**)&wql, g_Wql);
    cudaGetSymbolAddress((void**)&wkh, g_Wkh);
    cudaGetSymbolAddress((void**)&wkl, g_Wkl);

    cudaFuncSetAttribute(proj_dual, cudaFuncAttributeMaxDynamicSharedMemorySize, PSM_TOTAL);
    cudaFuncSetAttribute(attn_fused, cudaFuncAttributeMaxDynamicSharedMemorySize, SM_TOTAL);

    // ---- canonicalize counts, then fused pre-split + weight conversion ----
    prep_counts<<<1, 64>>>(nro, nre, nrf);
    presplit_all<<<B_ALL, 256>>>(ar, own, enemy);
    wconvert<<<dim3(KQ / 32, 8), 256>>>(Wq, KQ, wqh, wql);
    wconvert<<<dim3(256 / 32, 8), 256>>>(Wk, 256, wkh, wkl);

    // ---- Q and K projections in ONE launch (z=0 Q, z=1 K) ----
    proj_dual<<<dim3(2, MTOT / 128, 2), 256, PSM_TOTAL>>>(bq, bk);

    // ---- fused scores + mask + softmax (mask-skipping) ----
    attn_fused<<<dim3(UU / 64, BB), 256, SM_TOTAL>>>(out);
}

// round 16
// speedup vs baseline: 1.5507x; 1.0042x over previous
#include <cuda_runtime.h>
#include <cuda_bf16.h>
#include <cstdint>

// Problem constants
#define BB 64
#define UU 512
#define AE 1024
#define UE 256
#define AA 256           // head size
#define MTOT (BB*UU)     // 32768 rows
#define KQ 1280          // Q-proj K dim

// Pre-split inputs (bf16 hi/lo; x = hi + lo)
__device__ __nv_bfloat16 g_Ah[(size_t)MTOT * KQ], g_Al[(size_t)MTOT * KQ];   // concat(ar,own)
__device__ __nv_bfloat16 g_Eh[(size_t)MTOT * UE], g_El[(size_t)MTOT * UE];   // enemy
// Pre-transposed/split weights: Wt[n][ktot]
__device__ __nv_bfloat16 g_Wqh[256 * KQ], g_Wql[256 * KQ];
__device__ __nv_bfloat16 g_Wkh[256 * 256], g_Wkl[256 * 256];
// Q/K projections, bf16 hi/lo
__device__ __nv_bfloat16 g_Qhi[(size_t)MTOT * AA], g_Qlo[(size_t)MTOT * AA];
__device__ __nv_bfloat16 g_Khi[(size_t)MTOT * AA], g_Klo[(size_t)MTOT * AA];
// Canonicalized per-batch counts (consumed by proj/attn launches)
__device__ int g_fl[BB], g_ou[BB], g_en[BB];

// ---------------------------------------------------------------------------
// Adaptive int width (JAX w/o x64 silently emits int32 despite astype(int64)).
// ---------------------------------------------------------------------------
__device__ __forceinline__ bool counts_are_64bit(const int* p) {
    bool z = true;
    #pragma unroll
    for (int i = 1; i < 64; i += 2) z &= (p[i] == 0);
    return z;
}

// ---------------------------------------------------------------------------
// Helpers
// ---------------------------------------------------------------------------
__device__ __forceinline__ void split_bf16(float v, __nv_bfloat16& h, __nv_bfloat16& l) {
    h = __float2bfloat16(v);
    l = __float2bfloat16(v - __bfloat162float(h));
}
__device__ __forceinline__ void split2(float f0, float f1, uint32_t& hh, uint32_t& ll) {
    __nv_bfloat16 h0, l0, h1, l1;
    split_bf16(f0, h0, l0);
    split_bf16(f1, h1, l1);
    __nv_bfloat162 H; H.x = h0; H.y = h1;
    __nv_bfloat162 L; L.x = l0; L.y = l1;
    hh = *(uint32_t*)&H;
    ll = *(uint32_t*)&L;
}
__device__ __forceinline__ uint32_t smem_u32(const void* p) {
    return (uint32_t)__cvta_generic_to_shared(p);
}
__device__ __forceinline__ void cp16(void* dst, const void* src) {
    asm volatile("cp.async.cg.shared.global [%0], [%1], 16;"
                 :: "r"(smem_u32(dst)), "l"(src));
}
__device__ __forceinline__ void cp_commit() { asm volatile("cp.async.commit_group;"); }
template<int N> __device__ __forceinline__ void cp_wait() {
    asm volatile("cp.async.wait_group %0;" :: "n"(N));
}
__device__ __forceinline__ void ldmx4(uint32_t* r, const void* ptr) {
    asm volatile("ldmatrix.sync.aligned.m8n8.x4.shared.b16 {%0,%1,%2,%3}, [%4];"
                 : "=r"(r[0]), "=r"(r[1]), "=r"(r[2]), "=r"(r[3]) : "r"(smem_u32(ptr)));
}
__device__ __forceinline__ void mma_bf16(float* d, const uint32_t* a, uint32_t b0, uint32_t b1) {
    asm volatile("mma.sync.aligned.m16n8k16.row.col.f32.bf16.bf16.f32 "
                 "{%0,%1,%2,%3}, {%4,%5,%6,%7}, {%8,%9}, {%0,%1,%2,%3};"
                 : "+f"(d[0]), "+f"(d[1]), "+f"(d[2]), "+f"(d[3])
                 : "r"(a[0]), "r"(a[1]), "r"(a[2]), "r"(a[3]), "r"(b0), "r"(b1));
}

// ===========================================================================
// ONE prep kernel: [counts | wconvert(Wq) | wconvert(Wk) | presplit x3].
// presplit blocks read counts INLINE from raw buffers (no ordering needed);
// g_fl/g_ou/g_en written by block 0 are consumed only by later launches.
// ===========================================================================
#define T4_AR  (MTOT * (AE / 4))     // 8388608
#define T4_OWN (MTOT * (UE / 4))     // 2097152
#define B_AR   (T4_AR / 256)         // 32768 blocks
#define B_OWN  (T4_OWN / 256)        // 8192 blocks
#define B_SPLIT (B_AR + 2 * B_OWN)   // 49152
#define WQ_BLKS ((KQ / 32) * 8)      // 320
#define WK_BLKS ((256 / 32) * 8)     // 64
#define B_PREP (1 + WQ_BLKS + WK_BLKS + B_SPLIT)

__global__ void __launch_bounds__(256)
prep_all(const float* __restrict__ ar, const float* __restrict__ own,
         const float* __restrict__ enemy,
         const int* __restrict__ nro, const int* __restrict__ nre,
         const int* __restrict__ nrf,
         const float* __restrict__ Wq, const float* __restrict__ Wk)
{
    __shared__ float t[32][33];
    __shared__ int s_is64;

    const int blk = blockIdx.x;
    const int tid = threadIdx.x;

    // ---- region 0: canonicalize counts ----
    if (blk == 0) {
        if (tid < 64) {
            const bool is64 = counts_are_64bit(nro);
            const int idx = is64 ? 2 * tid : tid;
            g_ou[tid] = nro[idx];
            g_en[tid] = nre[idx];
            g_fl[tid] = nrf[idx];
        }
        return;
    }

    // ---- region 1: weight transpose + split ----
    if (blk < 1 + WQ_BLKS + WK_BLKS) {
        const float* W;
        __nv_bfloat16 *Wh, *Wl;
        int ktot, bx, by;
        if (blk < 1 + WQ_BLKS) {
            const int i = blk - 1;
            W = Wq; Wh = g_Wqh; Wl = g_Wql; ktot = KQ;
            bx = i % (KQ / 32); by = i / (KQ / 32);
        } else {
            const int i = blk - 1 - WQ_BLKS;
            W = Wk; Wh = g_Wkh; Wl = g_Wkl; ktot = 256;
            bx = i % (256 / 32); by = i / (256 / 32);
        }
        const int kb = bx * 32, nb = by * 32;
        const int tx = tid & 31, ty = tid >> 5;
        #pragma unroll
        for (int i = ty; i < 32; i += 8)
            t[i][tx] = W[(size_t)(kb + i) * 256 + nb + tx];
        __syncthreads();
        #pragma unroll
        for (int i = ty; i < 32; i += 8) {
            __nv_bfloat16 h, l;
            split_bf16(t[tx][i], h, l);
            Wh[(size_t)(nb + i) * ktot + kb + tx] = h;
            Wl[(size_t)(nb + i) * ktot + kb + tx] = l;
        }
        return;
    }

    // ---- region 2: input pre-split (inline count reads) ----
    const int sb = blk - 1 - WQ_BLKS - WK_BLKS;
    const float* src;
    __nv_bfloat16 *dh, *dl;
    int cols, ldd, off, mode, idx;

    if (sb < B_AR) {
        src = ar;    dh = g_Ah; dl = g_Al; cols = AE; ldd = KQ; off = 0;   mode = 0;
        idx = sb * 256 + tid;
    } else if (sb < B_AR + B_OWN) {
        src = own;   dh = g_Ah; dl = g_Al; cols = UE; ldd = KQ; off = AE;  mode = 0;
        idx = (sb - B_AR) * 256 + tid;
    } else {
        src = enemy; dh = g_Eh; dl = g_El; cols = UE; ldd = UE; off = 0;   mode = 1;
        idx = (sb - B_AR - B_OWN) * 256 + tid;
    }

    if (tid == 0) s_is64 = counts_are_64bit(nro) ? 1 : 0;
    __syncthreads();
    const int mul = s_is64 ? 2 : 1;

    const int c4 = cols >> 2;
    int row = idx / c4, c = (idx - row * c4) * 4;

    const int b = row >> 9;
    const int L = (row & 511) & ~127;      // 128-aligned local block start
    if (mode == 0) {
        const int ou = nro[mul * b], fl = nrf[mul * b];
        if (!(L < ou && L + 128 > fl)) return;
    } else {
        const int en = nre[mul * b];
        if (L >= en) return;
    }

    float4 v = *(const float4*)&src[(size_t)row * cols + c];
    uint32_t h0, l0, h1, l1;
    split2(v.x, v.y, h0, l0);
    split2(v.z, v.w, h1, l1);
    const size_t o = (size_t)row * ldd + off + c;
    uint2 H; H.x = h0; H.y = h1;
    uint2 L2; L2.x = l0; L2.y = l1;
    *(uint2*)&dh[o] = H;
    *(uint2*)&dl[o] = L2;
}

// ===========================================================================
// Dual projection GEMM (Q and K in ONE launch; z=0 -> Q, z=1 -> K):
//   Q = A[M,1280] @ Wq^T + bq ; K = E[M,256] @ Wk^T + bk   (bf16 split-3)
// Block 128(m) x 128(n), BK=32, 8 warps of 64x32. 2-stage cp.async ring.
// NOTE: do NOT force __launch_bounds__(256,2) — natural occupancy is already
// 2 CTA/SM; the forced reg cap spills accumulators (R13: 312 -> 463us).
// ===========================================================================
#define PLD 40                       // tile row stride (bf16): 80B, conflict-free
#define TILE_B (128 * PLD * 2)       // 10240 bytes per tile
#define STAGE_B (4 * TILE_B)         // Ah, Al, Wh, Wl
#define PSM_TOTAL (2 * STAGE_B)      // 81920

__global__ void __launch_bounds__(256)
proj_dual(const float* __restrict__ bq, const float* __restrict__ bk)
{
    extern __shared__ __align__(16) char sm[];

    const int z = blockIdx.z;                 // 0 = Q, 1 = K
    const int row0 = blockIdx.y * 128;
    {   // masked-block skip (block-uniform)
        const int b = row0 >> 9, local0 = row0 & 511;
        if (z == 0) {
            if (!(local0 < g_ou[b] && local0 + 128 > g_fl[b])) return;
        } else {
            if (local0 >= g_en[b]) return;
        }
    }

    const __nv_bfloat16* Abh = z ? g_Eh  : g_Ah;
    const __nv_bfloat16* Abl = z ? g_El  : g_Al;
    const __nv_bfloat16* Wth = z ? g_Wkh : g_Wqh;
    const __nv_bfloat16* Wtl = z ? g_Wkl : g_Wql;
    const float*         bias = z ? bk : bq;
    __nv_bfloat16* Chi = z ? g_Khi : g_Qhi;
    __nv_bfloat16* Clo = z ? g_Klo : g_Qlo;
    const int ktot = z ? UE : KQ;

    const int tid  = threadIdx.x;
    const int warp = tid >> 5, lane = tid & 31;
    const int col0 = blockIdx.x * 128;

    const int wm = (warp & 1) * 64;
    const int wn = (warp >> 1) * 32;

    const int u0 = tid * 2;

    auto prefetch = [&](int it) {
        char* buf = sm + (it & 1) * STAGE_B;
        const int kb = it * 32;
        #pragma unroll
        for (int j = 0; j < 2; ++j) {
            const int u = u0 + j;
            const int r = u >> 2;
            const int seg = (u & 3) * 8;
            char* dst = buf + r * (PLD * 2) + seg * 2;
            const size_t ga = (size_t)(row0 + r) * ktot + kb + seg;
            const size_t gw = (size_t)(col0 + r) * ktot + kb + seg;
            cp16(dst,                Abh + ga);
            cp16(dst + TILE_B,       Abl + ga);
            cp16(dst + 2 * TILE_B,   Wth + gw);
            cp16(dst + 3 * TILE_B,   Wtl + gw);
        }
        cp_commit();
    };

    prefetch(0);

    const int lrow = lane & 15;
    const int lcol = (lane >> 4) * 8;
    const int n_it = ktot / 32;

    float acc[4][4][4] = {};

    for (int it = 0; it < n_it; ++it) {
        const bool more = it + 1 < n_it;
        if (more) prefetch(it + 1);
        if (more) cp_wait<1>(); else cp_wait<0>();
        __syncthreads();

        const char* buf = sm + (it & 1) * STAGE_B;
        const __nv_bfloat16* Ah = (const __nv_bfloat16*)buf;
        const __nv_bfloat16* Al = (const __nv_bfloat16*)(buf + TILE_B);
        const __nv_bfloat16* Wh = (const __nv_bfloat16*)(buf + 2 * TILE_B);
        const __nv_bfloat16* Wl = (const __nv_bfloat16*)(buf + 3 * TILE_B);

        #pragma unroll
        for (int kc = 0; kc < 32; kc += 16) {
            uint32_t ah[4][4], al2[4][4], bh[2][4], bl[2][4];
            #pragma unroll
            for (int mi = 0; mi < 4; ++mi) {
                ldmx4(ah[mi],  &Ah[(wm + mi * 16 + lrow) * PLD + kc + lcol]);
                ldmx4(al2[mi], &Al[(wm + mi * 16 + lrow) * PLD + kc + lcol]);
            }
            #pragma unroll
            for (int ni = 0; ni < 2; ++ni) {
                ldmx4(bh[ni], &Wh[(wn + ni * 16 + lrow) * PLD + kc + lcol]);
                ldmx4(bl[ni], &Wl[(wn + ni * 16 + lrow) * PLD + kc + lcol]);
            }
            #pragma unroll
            for (int mi = 0; mi < 4; ++mi)
                #pragma unroll
                for (int ni = 0; ni < 2; ++ni)
                    #pragma unroll
                    for (int t = 0; t < 2; ++t) {
                        float* d = acc[mi][ni * 2 + t];
                        mma_bf16(d, ah[mi],  bh[ni][t], bh[ni][t + 2]);
                        mma_bf16(d, ah[mi],  bl[ni][t], bl[ni][t + 2]);
                        mma_bf16(d, al2[mi], bh[ni][t], bh[ni][t + 2]);
                    }
        }
        __syncthreads();
    }

    #pragma unroll
    for (int mi = 0; mi < 4; ++mi)
        #pragma unroll
        for (int p = 0; p < 4; ++p) {
            const int c = col0 + wn + p * 8 + (lane & 3) * 2;
            const float b0 = bias[c], b1 = bias[c + 1];
            #pragma unroll
            for (int h = 0; h < 2; ++h) {
                const int row = row0 + wm + mi * 16 + (lane >> 2) + h * 8;
                float v0 = acc[mi][p][h * 2 + 0] + b0;
                float v1 = acc[mi][p][h * 2 + 1] + b1;
                uint32_t hh, ll;
                split2(v0, v1, hh, ll);
                *(uint32_t*)&Chi[(size_t)row * AA + c] = hh;
                *(uint32_t*)&Clo[(size_t)row * AA + c] = ll;
            }
        }
}

// ===========================================================================
// Fused attention + softmax with mask-driven skipping (unchanged hot loop).
// ===========================================================================
#define LDQ (AA + 8)      // 264 bf16 -> row stride 528B (16B-aligned)
#define LDB 24
#define LDS 516

#define Q_BYTES    (64 * LDQ * 2)
#define STG_BYTES  (128 * LDB * 2)
#define SM_QH 0
#define SM_QL (SM_QH + Q_BYTES)
#define SM_B0 (SM_QL + Q_BYTES)
#define SM_S  (SM_B0 + 4 * STG_BYTES)
#define SM_TOTAL (SM_S + 64 * LDS * 4)

#define UNIFORM_P 0.001953125f   // 1/512

__global__ void __launch_bounds__(256)
attn_fused(float* __restrict__ out)
{
    extern __shared__ __align__(16) char sm[];
    __nv_bfloat16* Qh = (__nv_bfloat16*)(sm + SM_QH);
    __nv_bfloat16* Ql = (__nv_bfloat16*)(sm + SM_QL);
    float* S = (float*)(sm + SM_S);

    const int tid  = threadIdx.x;
    const int warp = tid >> 5, lane = tid & 31;
    const int b    = blockIdx.y;
    const int row0 = blockIdx.x * 64;

    const int fl = g_fl[b], ou = g_ou[b], en = g_en[b];
    float* outb = out + (size_t)b * UU * UU + (size_t)row0 * UU;

    // Fully-masked row block: softmax of ~0 logits == uniform. Write & leave.
    if (!(row0 < ou && row0 + 64 > fl)) {
        float4 u; u.x = u.y = u.z = u.w = UNIFORM_P;
        #pragma unroll
        for (int i = 0; i < 32; ++i)
            ((float4*)outb)[tid + i * 256] = u;
        return;
    }

    const int nch  = min(4, (en + 127) >> 7);   // live 128-key chunks
    const int n_it = nch * 16;

    const __nv_bfloat16* gQh = g_Qhi + (size_t)b * UU * AA;
    const __nv_bfloat16* gQl = g_Qlo + (size_t)b * UU * AA;
    const __nv_bfloat16* gKh = g_Khi + (size_t)b * UU * AA;
    const __nv_bfloat16* gKl = g_Klo + (size_t)b * UU * AA;

    const int krow = tid >> 1;
    const int koff = (tid & 1) * 8;
    auto prefetch = [&](int it) {
        const int kc = it >> 4, kk = (it & 15) * 16, buf = it & 1;
        __nv_bfloat16* dh = (__nv_bfloat16*)(sm + SM_B0 + (2 * buf + 0) * STG_BYTES);
        __nv_bfloat16* dl = (__nv_bfloat16*)(sm + SM_B0 + (2 * buf + 1) * STG_BYTES);
        const size_t g = (size_t)(kc * 128 + krow) * AA + kk + koff;
        cp16(&dh[krow * LDB + koff], &gKh[g]);
        cp16(&dl[krow * LDB + koff], &gKl[g]);
        cp_commit();
    };

    if (n_it > 0) {
        // Q tile via cp.async (group 0) — overlaps with K chunk-0 staging.
        #pragma unroll
        for (int i = 0; i < 8; ++i) {
            int idx = tid + i * 256;
            int r = idx >> 5;
            int c = (idx & 31) * 8;
            cp16(&Qh[r * LDQ + c], &gQh[(size_t)(row0 + r) * AA + c]);
            cp16(&Ql[r * LDQ + c], &gQl[(size_t)(row0 + r) * AA + c]);
        }
        cp_commit();
        prefetch(0);
    }

    const int wq = (warp & 1) * 32;
    const int wk = (warp >> 1) * 32;
    const int lrow = lane & 15;
    const int lcol = (lane >> 4) * 8;

    float acc[2][4][4] = {};

    for (int it = 0; it < n_it; ++it) {
        const bool more = it + 1 < n_it;
        if (more) prefetch(it + 1);
        if (more) cp_wait<1>(); else cp_wait<0>();
        __syncthreads();

        const int kc = it >> 4, buf = it & 1;
        const int kk = (it & 15) * 16;
        const __nv_bfloat16* Bhb = (const __nv_bfloat16*)(sm + SM_B0 + (2 * buf + 0) * STG_BYTES);
        const __nv_bfloat16* Blb = (const __nv_bfloat16*)(sm + SM_B0 + (2 * buf + 1) * STG_BYTES);

        uint32_t ah[2][4], al2[2][4], bh[2][4], bl[2][4];
        #pragma unroll
        for (int mi = 0; mi < 2; ++mi) {
            ldmx4(ah[mi],  &Qh[(wq + mi * 16 + lrow) * LDQ + kk + lcol]);
            ldmx4(al2[mi], &Ql[(wq + mi * 16 + lrow) * LDQ + kk + lcol]);
        }
        #pragma unroll
        for (int p = 0; p < 2; ++p) {
            ldmx4(bh[p], &Bhb[(wk + p * 16 + lrow) * LDB + lcol]);
            ldmx4(bl[p], &Blb[(wk + p * 16 + lrow) * LDB + lcol]);
        }
        #pragma unroll
        for (int mi = 0; mi < 2; ++mi)
            #pragma unroll
            for (int p = 0; p < 2; ++p)
                #pragma unroll
                for (int t = 0; t < 2; ++t) {
                    float* d = acc[mi][p * 2 + t];
                    mma_bf16(d, ah[mi],  bh[p][t], bh[p][t + 2]);
                    mma_bf16(d, ah[mi],  bl[p][t], bl[p][t + 2]);
                    mma_bf16(d, al2[mi], bh[p][t], bh[p][t + 2]);
                }

        if ((it & 15) == 15) {
            #pragma unroll
            for (int mi = 0; mi < 2; ++mi)
                #pragma unroll
                for (int ni = 0; ni < 4; ++ni) {
                    const int c = kc * 128 + wk + ni * 8 + (lane & 3) * 2;
                    #pragma unroll
                    for (int hh = 0; hh < 2; ++hh) {
                        const int row = wq + mi * 16 + (lane >> 2) + hh * 8;
                        float2 v;
                        v.x = acc[mi][ni][hh * 2 + 0] * 0.0625f;
                        v.y = acc[mi][ni][hh * 2 + 1] * 0.0625f;
                        *(float2*)&S[row * LDS + c] = v;
                        acc[mi][ni][hh * 2 + 0] = 0.f;
                        acc[mi][ni][hh * 2 + 1] = 0.f;
                    }
                }
        }
        __syncthreads();
    }

    // ---- masked softmax; masked logits are exactly 0 (matches s*1e-9) ----
    #pragma unroll 1
    for (int r8 = 0; r8 < 8; ++r8) {
        const int row = warp * 8 + r8;
        const int grow = row0 + row;
        const bool row_ok = (grow >= fl) && (grow < ou);

        if (!row_ok) {
            float4 u; u.x = u.y = u.z = u.w = UNIFORM_P;
            #pragma unroll
            for (int j = 0; j < 4; ++j)
                *(float4*)&outb[(size_t)row * UU + lane * 4 + j * 128] = u;
            continue;
        }

        float4 v[4];
        float m = 0.f;                      // masked zeros participate in max
        #pragma unroll
        for (int j = 0; j < 4; ++j) {
            const int c = lane * 4 + j * 128;
            float4 s = *(const float4*)&S[row * LDS + c];   // garbage ok; selected out
            #pragma unroll
            for (int e = 0; e < 4; ++e) {
                const bool ok = (c + e) < en;
                float x = ok ? (&s.x)[e] : 0.f;
                (&v[j].x)[e] = x;
                m = fmaxf(m, x);
            }
        }
        #pragma unroll
        for (int o = 16; o > 0; o >>= 1)
            m = fmaxf(m, __shfl_xor_sync(0xffffffffu, m, o));

        float sum = 0.f;
        #pragma unroll
        for (int j = 0; j < 4; ++j)
            #pragma unroll
            for (int e = 0; e < 4; ++e) {
                float x = __expf((&v[j].x)[e] - m);
                (&v[j].x)[e] = x;
                sum += x;
            }
        #pragma unroll
        for (int o = 16; o > 0; o >>= 1)
            sum += __shfl_xor_sync(0xffffffffu, sum, o);

        const float inv = 1.0f / sum;
        #pragma unroll
        for (int j = 0; j < 4; ++j) {
            v[j].x *= inv; v[j].y *= inv; v[j].z *= inv; v[j].w *= inv;
            *(float4*)&outb[(size_t)row * UU + lane * 4 + j * 128] = v[j];
        }
    }
}

// ---------------------------------------------------------------------------
extern "C" void kernel_launch(void* const* d_in, const int* in_sizes, int n_in,
                              void* d_out, int out_size)
{
    const float* ar    = (const float*)d_in[0];
    const float* own   = (const float*)d_in[1];
    const float* enemy = (const float*)d_in[2];
    const int* nro     = (const int*)d_in[3];
    const int* nre     = (const int*)d_in[4];
    const int* nrf     = (const int*)d_in[5];
    const float* Wq    = (const float*)d_in[6];
    const float* bq    = (const float*)d_in[7];
    const float* Wk    = (const float*)d_in[8];
    const float* bk    = (const float*)d_in[9];
    float* out = (float*)d_out;

    cudaFuncSetAttribute(proj_dual, cudaFuncAttributeMaxDynamicSharedMemorySize, PSM_TOTAL);
    cudaFuncSetAttribute(attn_fused, cudaFuncAttributeMaxDynamicSharedMemorySize, SM_TOTAL);

    // ---- ONE prep launch: counts + weight convert + input pre-split ----
    prep_all<<<B_PREP, 256>>>(ar, own, enemy, nro, nre, nrf, Wq, Wk);

    // ---- Q and K projections in ONE launch (z=0 Q, z=1 K) ----
    proj_dual<<<dim3(2, MTOT / 128, 2), 256, PSM_TOTAL>>>(bq, bk);

    // ---- fused scores + mask + softmax (mask-skipping) ----
    attn_fused<<<dim3(UU / 64, BB), 256, SM_TOTAL>>>(out);
}

// round 17
// speedup vs baseline: 1.6115x; 1.0392x over previous
#include <cuda_runtime.h>
#include <cuda_bf16.h>
#include <cstdint>

// Problem constants
#define BB 64
#define UU 512
#define AE 1024
#define UE 256
#define AA 256           // head size
#define MTOT (BB*UU)     // 32768 rows
#define KQ 1280          // Q-proj K dim

// Pre-split inputs (bf16 hi/lo; x = hi + lo)
__device__ __nv_bfloat16 g_Ah[(size_t)MTOT * KQ], g_Al[(size_t)MTOT * KQ];   // concat(ar,own)
__device__ __nv_bfloat16 g_Eh[(size_t)MTOT * UE], g_El[(size_t)MTOT * UE];   // enemy
// Pre-transposed/split weights: Wt[n][ktot]
__device__ __nv_bfloat16 g_Wqh[256 * KQ], g_Wql[256 * KQ];
__device__ __nv_bfloat16 g_Wkh[256 * 256], g_Wkl[256 * 256];
// Q/K projections, bf16 hi/lo
__device__ __nv_bfloat16 g_Qhi[(size_t)MTOT * AA], g_Qlo[(size_t)MTOT * AA];
__device__ __nv_bfloat16 g_Khi[(size_t)MTOT * AA], g_Klo[(size_t)MTOT * AA];
// Canonicalized per-batch counts (consumed by proj/attn launches)
__device__ int g_fl[BB], g_ou[BB], g_en[BB];

// ---------------------------------------------------------------------------
// Adaptive int width (JAX w/o x64 silently emits int32 despite astype(int64)).
// ---------------------------------------------------------------------------
__device__ __forceinline__ bool counts_are_64bit(const int* p) {
    bool z = true;
    #pragma unroll
    for (int i = 1; i < 64; i += 2) z &= (p[i] == 0);
    return z;
}

// ---------------------------------------------------------------------------
// Helpers
// ---------------------------------------------------------------------------
__device__ __forceinline__ void split_bf16(float v, __nv_bfloat16& h, __nv_bfloat16& l) {
    h = __float2bfloat16(v);
    l = __float2bfloat16(v - __bfloat162float(h));
}
__device__ __forceinline__ void split2(float f0, float f1, uint32_t& hh, uint32_t& ll) {
    __nv_bfloat16 h0, l0, h1, l1;
    split_bf16(f0, h0, l0);
    split_bf16(f1, h1, l1);
    __nv_bfloat162 H; H.x = h0; H.y = h1;
    __nv_bfloat162 L; L.x = l0; L.y = l1;
    hh = *(uint32_t*)&H;
    ll = *(uint32_t*)&L;
}
__device__ __forceinline__ uint32_t smem_u32(const void* p) {
    return (uint32_t)__cvta_generic_to_shared(p);
}
__device__ __forceinline__ void cp16(void* dst, const void* src) {
    asm volatile("cp.async.cg.shared.global [%0], [%1], 16;"
                 :: "r"(smem_u32(dst)), "l"(src));
}
__device__ __forceinline__ void cp_commit() { asm volatile("cp.async.commit_group;"); }
template<int N> __device__ __forceinline__ void cp_wait() {
    asm volatile("cp.async.wait_group %0;" :: "n"(N));
}
__device__ __forceinline__ void ldmx4(uint32_t* r, const void* ptr) {
    asm volatile("ldmatrix.sync.aligned.m8n8.x4.shared.b16 {%0,%1,%2,%3}, [%4];"
                 : "=r"(r[0]), "=r"(r[1]), "=r"(r[2]), "=r"(r[3]) : "r"(smem_u32(ptr)));
}
__device__ __forceinline__ void mma_bf16(float* d, const uint32_t* a, uint32_t b0, uint32_t b1) {
    asm volatile("mma.sync.aligned.m16n8k16.row.col.f32.bf16.bf16.f32 "
                 "{%0,%1,%2,%3}, {%4,%5,%6,%7}, {%8,%9}, {%0,%1,%2,%3};"
                 : "+f"(d[0]), "+f"(d[1]), "+f"(d[2]), "+f"(d[3])
                 : "r"(a[0]), "r"(a[1]), "r"(a[2]), "r"(a[3]), "r"(b0), "r"(b1));
}

// Convert+store 2 float4 (32B) -> hi/lo uint4 (16B each)
__device__ __forceinline__ void split8_store(const float4 v0, const float4 v1,
                                             __nv_bfloat16* dh, __nv_bfloat16* dl)
{
    uint32_t hh[4], ll[4];
    split2(v0.x, v0.y, hh[0], ll[0]);
    split2(v0.z, v0.w, hh[1], ll[1]);
    split2(v1.x, v1.y, hh[2], ll[2]);
    split2(v1.z, v1.w, hh[3], ll[3]);
    *(uint4*)dh = *(uint4*)hh;
    *(uint4*)dl = *(uint4*)ll;
}

// ===========================================================================
// ONE prep kernel: [counts | wconvert(Wq) | wconvert(Wk) | presplit x3].
// presplit uses 8-float granules + compile-time shift indexing (no idiv).
// ===========================================================================
#define T8_AR  (MTOT * (AE / 8))     // 4194304 granules
#define T8_OWN (MTOT * (UE / 8))     // 1048576
#define B_AR   (T8_AR / 256)         // 16384 blocks
#define B_OWN  (T8_OWN / 256)        // 4096 blocks
#define WQ_BLKS ((KQ / 32) * 8)      // 320
#define WK_BLKS ((256 / 32) * 8)     // 64
#define B_PREP (1 + WQ_BLKS + WK_BLKS + B_AR + 2 * B_OWN)

__global__ void __launch_bounds__(256)
prep_all(const float* __restrict__ ar, const float* __restrict__ own,
         const float* __restrict__ enemy,
         const int* __restrict__ nro, const int* __restrict__ nre,
         const int* __restrict__ nrf,
         const float* __restrict__ Wq, const float* __restrict__ Wk)
{
    __shared__ float t[32][33];
    __shared__ int s_is64;

    const int blk = blockIdx.x;
    const int tid = threadIdx.x;

    // ---- region 0: canonicalize counts ----
    if (blk == 0) {
        if (tid < 64) {
            const bool is64 = counts_are_64bit(nro);
            const int idx = is64 ? 2 * tid : tid;
            g_ou[tid] = nro[idx];
            g_en[tid] = nre[idx];
            g_fl[tid] = nrf[idx];
        }
        return;
    }

    // ---- region 1: weight transpose + split ----
    if (blk < 1 + WQ_BLKS + WK_BLKS) {
        const float* W;
        __nv_bfloat16 *Wh, *Wl;
        int ktot, bx, by;
        if (blk < 1 + WQ_BLKS) {
            const int i = blk - 1;
            W = Wq; Wh = g_Wqh; Wl = g_Wql; ktot = KQ;
            bx = i % (KQ / 32); by = i / (KQ / 32);
        } else {
            const int i = blk - 1 - WQ_BLKS;
            W = Wk; Wh = g_Wkh; Wl = g_Wkl; ktot = 256;
            bx = i % (256 / 32); by = i / (256 / 32);
        }
        const int kb = bx * 32, nb = by * 32;
        const int tx = tid & 31, ty = tid >> 5;
        #pragma unroll
        for (int i = ty; i < 32; i += 8)
            t[i][tx] = W[(size_t)(kb + i) * 256 + nb + tx];
        __syncthreads();
        #pragma unroll
        for (int i = ty; i < 32; i += 8) {
            __nv_bfloat16 h, l;
            split_bf16(t[tx][i], h, l);
            Wh[(size_t)(nb + i) * ktot + kb + tx] = h;
            Wl[(size_t)(nb + i) * ktot + kb + tx] = l;
        }
        return;
    }

    // ---- region 2: input pre-split; granule = 8 floats; shift indexing ----
    if (tid == 0) s_is64 = counts_are_64bit(nro) ? 1 : 0;
    __syncthreads();
    const int mul = s_is64 ? 2 : 1;

    const int sb = blk - 1 - WQ_BLKS - WK_BLKS;

    if (sb < B_AR) {
        // ar: cols=1024, 128 granules/row -> row = idx >> 7
        const int idx = sb * 256 + tid;
        const int row = idx >> 7;
        const int c = (idx & 127) * 8;
        const int b = row >> 9;
        const int L = (row & 511) & ~127;
        if (!(L < nro[mul * b] && L + 128 > nrf[mul * b])) return;
        const float4* s = (const float4*)&ar[(size_t)row * AE + c];
        const size_t o = (size_t)row * KQ + c;
        split8_store(s[0], s[1], &g_Ah[o], &g_Al[o]);
    } else if (sb < B_AR + B_OWN) {
        // own: cols=256, 32 granules/row -> row = idx >> 5
        const int idx = (sb - B_AR) * 256 + tid;
        const int row = idx >> 5;
        const int c = (idx & 31) * 8;
        const int b = row >> 9;
        const int L = (row & 511) & ~127;
        if (!(L < nro[mul * b] && L + 128 > nrf[mul * b])) return;
        const float4* s = (const float4*)&own[(size_t)row * UE + c];
        const size_t o = (size_t)row * KQ + AE + c;
        split8_store(s[0], s[1], &g_Ah[o], &g_Al[o]);
    } else {
        // enemy: cols=256 -> row = idx >> 5
        const int idx = (sb - B_AR - B_OWN) * 256 + tid;
        const int row = idx >> 5;
        const int c = (idx & 31) * 8;
        const int b = row >> 9;
        const int L = (row & 511) & ~127;
        if (L >= nre[mul * b]) return;
        const float4* s = (const float4*)&enemy[(size_t)row * UE + c];
        const size_t o = (size_t)row * UE + c;
        split8_store(s[0], s[1], &g_Eh[o], &g_El[o]);
    }
}

// ===========================================================================
// Dual projection GEMM (Q and K in ONE launch; z=0 -> Q, z=1 -> K):
//   Q = A[M,1280] @ Wq^T + bq ; K = E[M,256] @ Wk^T + bk   (bf16 split-3)
// Block 128(m) x 128(n), BK=32, 8 warps of 64x32. 2-stage cp.async ring.
// NOTE: do NOT force __launch_bounds__(256,2) — natural occupancy is already
// 2 CTA/SM; the forced reg cap spills accumulators (R13: 312 -> 463us).
// ===========================================================================
#define PLD 40                       // tile row stride (bf16): 80B, conflict-free
#define TILE_B (128 * PLD * 2)       // 10240 bytes per tile
#define STAGE_B (4 * TILE_B)         // Ah, Al, Wh, Wl
#define PSM_TOTAL (2 * STAGE_B)      // 81920

__global__ void __launch_bounds__(256)
proj_dual(const float* __restrict__ bq, const float* __restrict__ bk)
{
    extern __shared__ __align__(16) char sm[];

    const int z = blockIdx.z;                 // 0 = Q, 1 = K
    const int row0 = blockIdx.y * 128;
    {   // masked-block skip (block-uniform)
        const int b = row0 >> 9, local0 = row0 & 511;
        if (z == 0) {
            if (!(local0 < g_ou[b] && local0 + 128 > g_fl[b])) return;
        } else {
            if (local0 >= g_en[b]) return;
        }
    }

    const __nv_bfloat16* Abh = z ? g_Eh  : g_Ah;
    const __nv_bfloat16* Abl = z ? g_El  : g_Al;
    const __nv_bfloat16* Wth = z ? g_Wkh : g_Wqh;
    const __nv_bfloat16* Wtl = z ? g_Wkl : g_Wql;
    const float*         bias = z ? bk : bq;
    __nv_bfloat16* Chi = z ? g_Khi : g_Qhi;
    __nv_bfloat16* Clo = z ? g_Klo : g_Qlo;
    const int ktot = z ? UE : KQ;

    const int tid  = threadIdx.x;
    const int warp = tid >> 5, lane = tid & 31;
    const int col0 = blockIdx.x * 128;

    const int wm = (warp & 1) * 64;
    const int wn = (warp >> 1) * 32;

    const int u0 = tid * 2;

    auto prefetch = [&](int it) {
        char* buf = sm + (it & 1) * STAGE_B;
        const int kb = it * 32;
        #pragma unroll
        for (int j = 0; j < 2; ++j) {
            const int u = u0 + j;
            const int r = u >> 2;
            const int seg = (u & 3) * 8;
            char* dst = buf + r * (PLD * 2) + seg * 2;
            const size_t ga = (size_t)(row0 + r) * ktot + kb + seg;
            const size_t gw = (size_t)(col0 + r) * ktot + kb + seg;
            cp16(dst,                Abh + ga);
            cp16(dst + TILE_B,       Abl + ga);
            cp16(dst + 2 * TILE_B,   Wth + gw);
            cp16(dst + 3 * TILE_B,   Wtl + gw);
        }
        cp_commit();
    };

    prefetch(0);

    const int lrow = lane & 15;
    const int lcol = (lane >> 4) * 8;
    const int n_it = ktot / 32;

    float acc[4][4][4] = {};

    for (int it = 0; it < n_it; ++it) {
        const bool more = it + 1 < n_it;
        if (more) prefetch(it + 1);
        if (more) cp_wait<1>(); else cp_wait<0>();
        __syncthreads();

        const char* buf = sm + (it & 1) * STAGE_B;
        const __nv_bfloat16* Ah = (const __nv_bfloat16*)buf;
        const __nv_bfloat16* Al = (const __nv_bfloat16*)(buf + TILE_B);
        const __nv_bfloat16* Wh = (const __nv_bfloat16*)(buf + 2 * TILE_B);
        const __nv_bfloat16* Wl = (const __nv_bfloat16*)(buf + 3 * TILE_B);

        #pragma unroll
        for (int kc = 0; kc < 32; kc += 16) {
            uint32_t ah[4][4], al2[4][4], bh[2][4], bl[2][4];
            #pragma unroll
            for (int mi = 0; mi < 4; ++mi) {
                ldmx4(ah[mi],  &Ah[(wm + mi * 16 + lrow) * PLD + kc + lcol]);
                ldmx4(al2[mi], &Al[(wm + mi * 16 + lrow) * PLD + kc + lcol]);
            }
            #pragma unroll
            for (int ni = 0; ni < 2; ++ni) {
                ldmx4(bh[ni], &Wh[(wn + ni * 16 + lrow) * PLD + kc + lcol]);
                ldmx4(bl[ni], &Wl[(wn + ni * 16 + lrow) * PLD + kc + lcol]);
            }
            #pragma unroll
            for (int mi = 0; mi < 4; ++mi)
                #pragma unroll
                for (int ni = 0; ni < 2; ++ni)
                    #pragma unroll
                    for (int t = 0; t < 2; ++t) {
                        float* d = acc[mi][ni * 2 + t];
                        mma_bf16(d, ah[mi],  bh[ni][t], bh[ni][t + 2]);
                        mma_bf16(d, ah[mi],  bl[ni][t], bl[ni][t + 2]);
                        mma_bf16(d, al2[mi], bh[ni][t], bh[ni][t + 2]);
                    }
        }
        __syncthreads();
    }

    #pragma unroll
    for (int mi = 0; mi < 4; ++mi)
        #pragma unroll
        for (int p = 0; p < 4; ++p) {
            const int c = col0 + wn + p * 8 + (lane & 3) * 2;
            const float b0 = bias[c], b1 = bias[c + 1];
            #pragma unroll
            for (int h = 0; h < 2; ++h) {
                const int row = row0 + wm + mi * 16 + (lane >> 2) + h * 8;
                float v0 = acc[mi][p][h * 2 + 0] + b0;
                float v1 = acc[mi][p][h * 2 + 1] + b1;
                uint32_t hh, ll;
                split2(v0, v1, hh, ll);
                *(uint32_t*)&Chi[(size_t)row * AA + c] = hh;
                *(uint32_t*)&Clo[(size_t)row * AA + c] = ll;
            }
        }
}

// ===========================================================================
// Fused attention + softmax with mask-driven skipping (unchanged hot loop).
// ===========================================================================
#define LDQ (AA + 8)      // 264 bf16 -> row stride 528B (16B-aligned)
#define LDB 24
#define LDS 516

#define Q_BYTES    (64 * LDQ * 2)
#define STG_BYTES  (128 * LDB * 2)
#define SM_QH 0
#define SM_QL (SM_QH + Q_BYTES)
#define SM_B0 (SM_QL + Q_BYTES)
#define SM_S  (SM_B0 + 4 * STG_BYTES)
#define SM_TOTAL (SM_S + 64 * LDS * 4)

#define UNIFORM_P 0.001953125f   // 1/512

__global__ void __launch_bounds__(256)
attn_fused(float* __restrict__ out)
{
    extern __shared__ __align__(16) char sm[];
    __nv_bfloat16* Qh = (__nv_bfloat16*)(sm + SM_QH);
    __nv_bfloat16* Ql = (__nv_bfloat16*)(sm + SM_QL);
    float* S = (float*)(sm + SM_S);

    const int tid  = threadIdx.x;
    const int warp = tid >> 5, lane = tid & 31;
    const int b    = blockIdx.y;
    const int row0 = blockIdx.x * 64;

    const int fl = g_fl[b], ou = g_ou[b], en = g_en[b];
    float* outb = out + (size_t)b * UU * UU + (size_t)row0 * UU;

    // Fully-masked row block: softmax of ~0 logits == uniform. Write & leave.
    if (!(row0 < ou && row0 + 64 > fl)) {
        float4 u; u.x = u.y = u.z = u.w = UNIFORM_P;
        #pragma unroll
        for (int i = 0; i < 32; ++i)
            ((float4*)outb)[tid + i * 256] = u;
        return;
    }

    const int nch  = min(4, (en + 127) >> 7);   // live 128-key chunks
    const int n_it = nch * 16;

    const __nv_bfloat16* gQh = g_Qhi + (size_t)b * UU * AA;
    const __nv_bfloat16* gQl = g_Qlo + (size_t)b * UU * AA;
    const __nv_bfloat16* gKh = g_Khi + (size_t)b * UU * AA;
    const __nv_bfloat16* gKl = g_Klo + (size_t)b * UU * AA;

    const int krow = tid >> 1;
    const int koff = (tid & 1) * 8;
    auto prefetch = [&](int it) {
        const int kc = it >> 4, kk = (it & 15) * 16, buf = it & 1;
        __nv_bfloat16* dh = (__nv_bfloat16*)(sm + SM_B0 + (2 * buf + 0) * STG_BYTES);
        __nv_bfloat16* dl = (__nv_bfloat16*)(sm + SM_B0 + (2 * buf + 1) * STG_BYTES);
        const size_t g = (size_t)(kc * 128 + krow) * AA + kk + koff;
        cp16(&dh[krow * LDB + koff], &gKh[g]);
        cp16(&dl[krow * LDB + koff], &gKl[g]);
        cp_commit();
    };

    if (n_it > 0) {
        // Q tile via cp.async (group 0) — overlaps with K chunk-0 staging.
        #pragma unroll
        for (int i = 0; i < 8; ++i) {
            int idx = tid + i * 256;
            int r = idx >> 5;
            int c = (idx & 31) * 8;
            cp16(&Qh[r * LDQ + c], &gQh[(size_t)(row0 + r) * AA + c]);
            cp16(&Ql[r * LDQ + c], &gQl[(size_t)(row0 + r) * AA + c]);
        }
        cp_commit();
        prefetch(0);
    }

    const int wq = (warp & 1) * 32;
    const int wk = (warp >> 1) * 32;
    const int lrow = lane & 15;
    const int lcol = (lane >> 4) * 8;

    float acc[2][4][4] = {};

    for (int it = 0; it < n_it; ++it) {
        const bool more = it + 1 < n_it;
        if (more) prefetch(it + 1);
        if (more) cp_wait<1>(); else cp_wait<0>();
        __syncthreads();

        const int kc = it >> 4, buf = it & 1;
        const int kk = (it & 15) * 16;
        const __nv_bfloat16* Bhb = (const __nv_bfloat16*)(sm + SM_B0 + (2 * buf + 0) * STG_BYTES);
        const __nv_bfloat16* Blb = (const __nv_bfloat16*)(sm + SM_B0 + (2 * buf + 1) * STG_BYTES);

        uint32_t ah[2][4], al2[2][4], bh[2][4], bl[2][4];
        #pragma unroll
        for (int mi = 0; mi < 2; ++mi) {
            ldmx4(ah[mi],  &Qh[(wq + mi * 16 + lrow) * LDQ + kk + lcol]);
            ldmx4(al2[mi], &Ql[(wq + mi * 16 + lrow) * LDQ + kk + lcol]);
        }
        #pragma unroll
        for (int p = 0; p < 2; ++p) {
            ldmx4(bh[p], &Bhb[(wk + p * 16 + lrow) * LDB + lcol]);
            ldmx4(bl[p], &Blb[(wk + p * 16 + lrow) * LDB + lcol]);
        }
        #pragma unroll
        for (int mi = 0; mi < 2; ++mi)
            #pragma unroll
            for (int p = 0; p < 2; ++p)
                #pragma unroll
                for (int t = 0; t < 2; ++t) {
                    float* d = acc[mi][p * 2 + t];
                    mma_bf16(d, ah[mi],  bh[p][t], bh[p][t + 2]);
                    mma_bf16(d, ah[mi],  bl[p][t], bl[p][t + 2]);
                    mma_bf16(d, al2[mi], bh[p][t], bh[p][t + 2]);
                }

        if ((it & 15) == 15) {
            #pragma unroll
            for (int mi = 0; mi < 2; ++mi)
                #pragma unroll
                for (int ni = 0; ni < 4; ++ni) {
                    const int c = kc * 128 + wk + ni * 8 + (lane & 3) * 2;
                    #pragma unroll
                    for (int hh = 0; hh < 2; ++hh) {
                        const int row = wq + mi * 16 + (lane >> 2) + hh * 8;
                        float2 v;
                        v.x = acc[mi][ni][hh * 2 + 0] * 0.0625f;
                        v.y = acc[mi][ni][hh * 2 + 1] * 0.0625f;
                        *(float2*)&S[row * LDS + c] = v;
                        acc[mi][ni][hh * 2 + 0] = 0.f;
                        acc[mi][ni][hh * 2 + 1] = 0.f;
                    }
                }
        }
        __syncthreads();
    }

    // ---- masked softmax; masked logits are exactly 0 (matches s*1e-9) ----
    #pragma unroll 1
    for (int r8 = 0; r8 < 8; ++r8) {
        const int row = warp * 8 + r8;
        const int grow = row0 + row;
        const bool row_ok = (grow >= fl) && (grow < ou);

        if (!row_ok) {
            float4 u; u.x = u.y = u.z = u.w = UNIFORM_P;
            #pragma unroll
            for (int j = 0; j < 4; ++j)
                *(float4*)&outb[(size_t)row * UU + lane * 4 + j * 128] = u;
            continue;
        }

        float4 v[4];
        float m = 0.f;                      // masked zeros participate in max
        #pragma unroll
        for (int j = 0; j < 4; ++j) {
            const int c = lane * 4 + j * 128;
            float4 s = *(const float4*)&S[row * LDS + c];   // garbage ok; selected out
            #pragma unroll
            for (int e = 0; e < 4; ++e) {
                const bool ok = (c + e) < en;
                float x = ok ? (&s.x)[e] : 0.f;
                (&v[j].x)[e] = x;
                m = fmaxf(m, x);
            }
        }
        #pragma unroll
        for (int o = 16; o > 0; o >>= 1)
            m = fmaxf(m, __shfl_xor_sync(0xffffffffu, m, o));

        float sum = 0.f;
        #pragma unroll
        for (int j = 0; j < 4; ++j)
            #pragma unroll
            for (int e = 0; e < 4; ++e) {
                float x = __expf((&v[j].x)[e] - m);
                (&v[j].x)[e] = x;
                sum += x;
            }
        #pragma unroll
        for (int o = 16; o > 0; o >>= 1)
            sum += __shfl_xor_sync(0xffffffffu, sum, o);

        const float inv = 1.0f / sum;
        #pragma unroll
        for (int j = 0; j < 4; ++j) {
            v[j].x *= inv; v[j].y *= inv; v[j].z *= inv; v[j].w *= inv;
            *(float4*)&outb[(size_t)row * UU + lane * 4 + j * 128] = v[j];
        }
    }
}

// ---------------------------------------------------------------------------
extern "C" void kernel_launch(void* const* d_in, const int* in_sizes, int n_in,
                              void* d_out, int out_size)
{
    const float* ar    = (const float*)d_in[0];
    const float* own   = (const float*)d_in[1];
    const float* enemy = (const float*)d_in[2];
    const int* nro     = (const int*)d_in[3];
    const int* nre     = (const int*)d_in[4];
    const int* nrf     = (const int*)d_in[5];
    const float* Wq    = (const float*)d_in[6];
    const float* bq    = (const float*)d_in[7];
    const float* Wk    = (const float*)d_in[8];
    const float* bk    = (const float*)d_in[9];
    float* out = (float*)d_out;

    cudaFuncSetAttribute(proj_dual, cudaFuncAttributeMaxDynamicSharedMemorySize, PSM_TOTAL);
    cudaFuncSetAttribute(attn_fused, cudaFuncAttributeMaxDynamicSharedMemorySize, SM_TOTAL);

    // ---- ONE prep launch: counts + weight convert + input pre-split ----
    prep_all<<<B_PREP, 256>>>(ar, own, enemy, nro, nre, nrf, Wq, Wk);

    // ---- Q and K projections in ONE launch (z=0 Q, z=1 K) ----
    proj_dual<<<dim3(2, MTOT / 128, 2), 256, PSM_TOTAL>>>(bq, bk);

    // ---- fused scores + mask + softmax (mask-skipping) ----
    attn_fused<<<dim3(UU / 64, BB), 256, SM_TOTAL>>>(out);
}